// round 9
// baseline (speedup 1.0000x reference)
#include <cuda_runtime.h>
#include <cuda_bf16.h>
#include <math.h>
#include <stdint.h>

#define BB 128
#define TT 64
#define EE 512
#define HH 512
#define VV 10000
#define FIN 2048
#define TB (TT*BB)   /* 8192 */
#define NT 79        /* N tiles of 128 covering 10000 (padded to 10112) */

// ---------------- scratch (static device globals; no runtime alloc) ----------------
__device__ float g_f[BB*EE];
__device__ float g_feats[BB*EE];
__device__ float g_x[TT*BB*EE];
__device__ float g_h[BB*HH];
__device__ float g_al[BB*HH];
__device__ float g_aw[BB*HH];
__device__ float g_inp[BB*HH];
__device__ float g_gh[BB*3*HH];
__device__ float g_gx[BB*3*HH];
__device__ float g_packed[TB*HH];
__device__ __nv_bfloat16 g_pk16[TB*512];
__device__ __nv_bfloat16 g_w16[NT*128*512];

__device__ __forceinline__ float4 ld4(const float* p){ return *(const float4*)p; }

__device__ __forceinline__ uint32_t smem_u32(const void* p){
    uint32_t a;
    asm("{ .reg .u64 t; cvta.to.shared.u64 t, %1; cvt.u32.u64 %0, t; }" : "=r"(a) : "l"(p));
    return a;
}
__device__ __forceinline__ void ldm4(uint32_t* r, uint32_t addr){
    asm volatile("ldmatrix.sync.aligned.m8n8.x4.shared.b16 {%0,%1,%2,%3}, [%4];"
        : "=r"(r[0]),"=r"(r[1]),"=r"(r[2]),"=r"(r[3]) : "r"(addr));
}
__device__ __forceinline__ void mma16816(float* c, const uint32_t* a, uint32_t b0, uint32_t b1){
    asm volatile("mma.sync.aligned.m16n8k16.row.col.f32.bf16.bf16.f32 "
        "{%0,%1,%2,%3}, {%4,%5,%6,%7}, {%8,%9}, {%0,%1,%2,%3};"
        : "+f"(c[0]),"+f"(c[1]),"+f"(c[2]),"+f"(c[3])
        : "r"(a[0]),"r"(a[1]),"r"(a[2]),"r"(a[3]), "r"(b0),"r"(b1));
}

// ---------------- small fp32 GEMM (recurrence) ----------------
__device__ __forceinline__ float4 fetchA4(int mode, const float* A0, int m, int kk, int K){
    if (mode == 0) return ld4(&A0[m*K + kk]);
    if (kk < 512)  return ld4(&A0[(m<<9) + kk]);
    int o = (m<<9) + (kk - 512);
    if (mode == 1) return ld4(&g_h[o]);
    float4 a = ld4(&g_feats[o]); float4 w = ld4(&g_aw[o]);
    return make_float4(a.x*w.x, a.y*w.y, a.z*w.z, a.w*w.w);
}

__device__ void gemm_dev(float (*As)[132], float (*Ws)[68],
                         int tile, int split, int nsplit, int mode,
                         const float* __restrict__ A0, const float* __restrict__ W,
                         const float* __restrict__ bias, float* __restrict__ C,
                         int N, int K)
{
    const int tid = threadIdx.x;
    const int n0 = tile * 64;
    const int kChunk = K / nsplit;
    const int kBeg = split * kChunk, kEnd = kBeg + kChunk;
    const int cx = tid & 15;
    const int ry = tid >> 4;

    float acc[8][4];
    for (int i=0;i<8;i++)
        for (int j=0;j<4;j++)
            acc[i][j]=0.f;

    for (int k0 = kBeg; k0 < kEnd; k0 += 32) {
        #pragma unroll
        for (int i=0;i<4;i++){
            int idx = tid + i*256;
            int m = idx >> 3, q = idx & 7;
            float4 v = fetchA4(mode, A0, m, k0 + 4*q, K);
            As[4*q+0][m]=v.x; As[4*q+1][m]=v.y; As[4*q+2][m]=v.z; As[4*q+3][m]=v.w;
        }
        #pragma unroll
        for (int i=0;i<2;i++){
            int idx = tid + i*256;
            int n = idx >> 3, q = idx & 7;
            float4 v = ld4(&W[(n0+n)*K + k0 + 4*q]);
            Ws[4*q+0][n]=v.x; Ws[4*q+1][n]=v.y; Ws[4*q+2][n]=v.z; Ws[4*q+3][n]=v.w;
        }
        __syncthreads();
        #pragma unroll
        for (int k=0;k<32;k++){
            float4 a0 = ld4(&As[k][8*ry]);
            float4 a1 = ld4(&As[k][8*ry+4]);
            float4 w  = ld4(&Ws[k][4*cx]);
            float av[8] = {a0.x,a0.y,a0.z,a0.w,a1.x,a1.y,a1.z,a1.w};
            float wv[4] = {w.x,w.y,w.z,w.w};
            #pragma unroll
            for(int i=0;i<8;i++)
              #pragma unroll
              for(int j=0;j<4;j++)
                acc[i][j] = fmaf(av[i], wv[j], acc[i][j]);
        }
        __syncthreads();
    }
    #pragma unroll
    for(int i=0;i<8;i++){
        int m = 8*ry + i;
        #pragma unroll
        for(int j=0;j<4;j++){
            int n = n0 + 4*cx + j;
            float v = acc[i][j];
            if (split == 0) v += bias[n];
            if (nsplit == 1) C[m*N + n] = v;
            else atomicAdd(&C[m*N + n], v);
        }
    }
}

#define GEMM_SHARED __shared__ float As[32][132]; __shared__ float Ws[32][68];

// ---------------- one-time kernels ----------------
__global__ void zero_init(){
    int stride = gridDim.x*blockDim.x;
    int i0 = blockIdx.x*blockDim.x + threadIdx.x;
    for (int i=i0;i<BB*EE;i+=stride)   g_f[i]=0.f;
    for (int i=i0;i<BB*HH;i+=stride)   g_al[i]=0.f;
    for (int i=i0;i<BB*3*HH;i+=stride) g_gh[i]=0.f;
}

__global__ void cvt_w(const float* __restrict__ outW){
    int stride = gridDim.x*blockDim.x;
    for (int i = blockIdx.x*blockDim.x + threadIdx.x; i < NT*128*512; i += stride){
        int r = i >> 9;
        g_w16[i] = __float2bfloat16(r < VV ? outW[i] : 0.f);
    }
}

__global__ void cvt_pk(){
    int stride = gridDim.x*blockDim.x;
    for (int i = blockIdx.x*blockDim.x + threadIdx.x; i < TB*512; i += stride)
        g_pk16[i] = __float2bfloat16(g_packed[i]);
}

__global__ void fc_kernel(const float* __restrict__ features,
                          const float* __restrict__ fcW, const float* __restrict__ fcb){
    GEMM_SHARED
    int tile = blockIdx.x & 7, split = blockIdx.x >> 3;
    gemm_dev(As, Ws, tile, split, 16, 0, features, fcW, fcb, g_f, EE, FIN);
}

__global__ void bn_kernel(const float* __restrict__ gamma, const float* __restrict__ beta){
    int j = threadIdx.x;
    float s = 0.f;
    for (int b=0;b<BB;b++) s += g_f[b*EE + j];
    float mu = s * (1.f/BB);
    float v = 0.f;
    for (int b=0;b<BB;b++){ float d = g_f[b*EE+j]-mu; v += d*d; }
    float rstd = rsqrtf(v*(1.f/BB) + 1e-5f);
    float ga = gamma[j], be = beta[j];
    for (int b=0;b<BB;b++)
        g_feats[b*EE+j] = ga*(g_f[b*EE+j]-mu)*rstd + be;
}

__global__ void prep_kernel(const int* __restrict__ captions,
                            const float* __restrict__ embed_W,
                            const float* __restrict__ h0){
    int stride = gridDim.x*blockDim.x;
    for (int gi = blockIdx.x*blockDim.x + threadIdx.x; gi < TT*BB*EE; gi += stride){
        int t = gi >> 16;          // BB*EE = 65536
        int idx = gi & 65535;
        int b = idx >> 9, e = idx & 511;
        float v;
        if (t == 0) v = g_feats[idx];
        else { int cap = captions[b*TT + (t-1)]; v = embed_W[cap*EE + e]; }
        g_x[gi] = v;
    }
    for (int i = blockIdx.x*blockDim.x + threadIdx.x; i < BB*HH; i += stride)
        g_h[i] = h0[i];
}

// ---------------- per-step kernels ----------------
__global__ void step_k1(const float* __restrict__ attn_W, const float* __restrict__ attn_b,
                        const float* __restrict__ whh, const float* __restrict__ bhh, int t){
    GEMM_SHARED
    for (int idx = blockIdx.x*blockDim.x + threadIdx.x; idx < BB*HH; idx += gridDim.x*blockDim.x)
        g_inp[idx] = 0.f;
    const float* x = g_x + t*(BB*EE);
    if (blockIdx.x < 64) {
        int tile = blockIdx.x & 7, split = blockIdx.x >> 3;
        gemm_dev(As, Ws, tile, split, 8, 1, x, attn_W, attn_b, g_al, HH, 1024);
    } else {
        int i = blockIdx.x - 64;
        int tile = i % 24, split = i / 24;
        gemm_dev(As, Ws, tile, split, 4, 0, g_h, whh, bhh, g_gh, 3*HH, HH);
    }
}

__global__ void step_softmax(){
    __shared__ float red[256];
    int b = blockIdx.x, tid = threadIdx.x;
    float v0 = g_al[b*512 + tid], v1 = g_al[b*512 + 256 + tid];
    float m = fmaxf(v0, v1);
    red[tid] = m; __syncthreads();
    for (int s=128; s>0; s>>=1){ if(tid<s) red[tid] = fmaxf(red[tid], red[tid+s]); __syncthreads(); }
    float mx = red[0]; __syncthreads();
    float e0 = expf(v0-mx), e1 = expf(v1-mx);
    red[tid] = e0+e1; __syncthreads();
    for (int s=128; s>0; s>>=1){ if(tid<s) red[tid]+=red[tid+s]; __syncthreads(); }
    float inv = 1.f/red[0];
    g_aw[b*512+tid]     = e0*inv;
    g_aw[b*512+256+tid] = e1*inv;
}

__global__ void step_k2(const float* __restrict__ comb_W, const float* __restrict__ comb_b, int t){
    GEMM_SHARED
    for (int idx = blockIdx.x*blockDim.x + threadIdx.x; idx < BB*3*HH; idx += gridDim.x*blockDim.x)
        g_gx[idx] = 0.f;
    const float* x = g_x + t*(BB*EE);
    int tile = blockIdx.x & 7, split = blockIdx.x >> 3;
    gemm_dev(As, Ws, tile, split, 8, 2, x, comb_W, comb_b, g_inp, HH, 1024);
}

__global__ void step_k3a(const float* __restrict__ wih, const float* __restrict__ bih){
    GEMM_SHARED
    int tile = blockIdx.x % 24, split = blockIdx.x / 24;
    gemm_dev(As, Ws, tile, split, 4, 0, g_inp, wih, bih, g_gx, 3*HH, HH);
}

__global__ void step_k3b(float* __restrict__ out_hidden, int t){
    int idx = blockIdx.x*blockDim.x + threadIdx.x;
    int b = idx >> 9, j = idx & 511;
    int g = b*1536 + j;
    float xr = g_gx[g], xz = g_gx[g+512], xn = g_gx[g+1024];
    float hr = g_gh[g], hz = g_gh[g+512], hn = g_gh[g+1024];
    float hx = g_h[idx];
    float r = 1.f/(1.f+expf(-(xr+hr)));
    float z = 1.f/(1.f+expf(-(xz+hz)));
    float nt = tanhf(xn + r*hn);
    float h = (1.f - z)*nt + z*hx;
    g_h[idx] = h;
    out_hidden[b*(TT*HH) + t*HH + j] = h;
    g_packed[(t*BB + b)*HH + j] = h;
    g_al[idx] = 0.f;
    g_gh[g] = 0.f; g_gh[g+512] = 0.f; g_gh[g+1024] = 0.f;
}

// ---------------- HMMA (mma.sync bf16) logits GEMM ----------------
// C[8192,10000] = packed(bf16) @ outW(bf16)^T + bias, fp32 accum.
// CTA tile 128x128, 8 warps (4M x 2N), warp tile 32x64, K chunks of 64.
#define APAD 72   /* bf16 row stride: 144B -> 4-bank shift per row, ldmatrix conflict-free */

__global__ __launch_bounds__(256) void out_gemm_mma(const float* __restrict__ outb,
                                                    float* __restrict__ logits){
    __shared__ __nv_bfloat16 Asm[128][APAD];
    __shared__ __nv_bfloat16 Bsm[128][APAD];
    __shared__ float s_bias[128];

    const int tid = threadIdx.x;
    const int lane = tid & 31, wid = tid >> 5;
    const int wm = wid & 3, wn = wid >> 2;      // 4 x 2 warp grid
    const int m0 = blockIdx.y * 128, n0 = blockIdx.x * 128;

    if (tid < 128){ int n = n0 + tid; s_bias[tid] = (n < VV) ? outb[n] : 0.f; }

    float acc[2][8][4];
    #pragma unroll
    for (int i=0;i<2;i++)
        #pragma unroll
        for (int j=0;j<8;j++)
            #pragma unroll
            for (int q=0;q<4;q++) acc[i][j][q]=0.f;

    const __nv_bfloat16* Ag = g_pk16 + (size_t)m0 * 512;
    const __nv_bfloat16* Bg = g_w16  + (size_t)n0 * 512;

    // per-thread ldmatrix source addresses (row/khalf pattern shared by A and B)
    const int lrow = lane & 15, lkh = (lane >> 4) * 8;

    for (int c = 0; c < 8; c++){
        // load 128x64 bf16 chunk of A and B into smem (4 uint4 per thread each)
        #pragma unroll
        for (int j = 0; j < 4; j++){
            int idx = tid + j*256;
            int r = idx >> 3, cv = idx & 7;
            *(uint4*)&Asm[r][cv*8] = *(const uint4*)(Ag + (size_t)r*512 + c*64 + cv*8);
            *(uint4*)&Bsm[r][cv*8] = *(const uint4*)(Bg + (size_t)r*512 + c*64 + cv*8);
        }
        __syncthreads();
        #pragma unroll
        for (int ks = 0; ks < 4; ks++){
            int kk = ks*16;
            uint32_t a[2][4];
            #pragma unroll
            for (int mt=0; mt<2; mt++){
                uint32_t ad = smem_u32(&Asm[wm*32 + mt*16 + lrow][kk + lkh]);
                ldm4(a[mt], ad);
            }
            uint32_t b[4][4];
            #pragma unroll
            for (int nt=0; nt<4; nt++){
                uint32_t bd = smem_u32(&Bsm[wn*64 + nt*16 + lrow][kk + lkh]);
                ldm4(b[nt], bd);
            }
            #pragma unroll
            for (int mt=0; mt<2; mt++)
                #pragma unroll
                for (int nt=0; nt<4; nt++){
                    mma16816(acc[mt][nt*2+0], a[mt], b[nt][0], b[nt][2]);
                    mma16816(acc[mt][nt*2+1], a[mt], b[nt][1], b[nt][3]);
                }
        }
        __syncthreads();
    }

    // epilogue: thread holds (row = lane>>2 [+8], col = (lane&3)*2 [+1]) per 16x8 tile
    const int r0 = lane >> 2, c2 = (lane & 3) * 2;
    #pragma unroll
    for (int mt=0; mt<2; mt++){
        int row = m0 + wm*32 + mt*16 + r0;
        #pragma unroll
        for (int nt=0; nt<8; nt++){
            int lcol = wn*64 + nt*8 + c2;
            int col  = n0 + lcol;
            if (col < VV){
                float2 v0, v1;
                v0.x = acc[mt][nt][0] + s_bias[lcol];
                v0.y = acc[mt][nt][1] + s_bias[lcol+1];
                v1.x = acc[mt][nt][2] + s_bias[lcol];
                v1.y = acc[mt][nt][3] + s_bias[lcol+1];
                *(float2*)&logits[(size_t)row * VV + col] = v0;
                *(float2*)&logits[(size_t)(row+8) * VV + col] = v1;
            }
        }
    }
}

__global__ void lsm_kernel(float* __restrict__ logits){
    __shared__ float buf[VV];
    __shared__ float red[256];
    int row = blockIdx.x, tid = threadIdx.x;
    float* p = logits + (size_t)row*VV;
    float m = -1e30f;
    for (int j=tid;j<VV;j+=256){ float v = p[j]; buf[j]=v; m = fmaxf(m,v); }
    red[tid]=m; __syncthreads();
    for (int s=128;s;s>>=1){ if(tid<s) red[tid]=fmaxf(red[tid],red[tid+s]); __syncthreads(); }
    float mx = red[0]; __syncthreads();
    float s=0.f;
    for (int j=tid;j<VV;j+=256) s += expf(buf[j]-mx);
    red[tid]=s; __syncthreads();
    for (int st=128;st;st>>=1){ if(tid<st) red[tid]+=red[tid+st]; __syncthreads(); }
    float lse = mx + logf(red[0]);
    for (int j=tid;j<VV;j+=256) p[j] = buf[j]-lse;
}

// ---------------- launch ----------------
extern "C" void kernel_launch(void* const* d_in, const int* in_sizes, int n_in,
                              void* d_out, int out_size){
    const float* features = (const float*)d_in[0];
    const int*   captions = (const int*)  d_in[1];
    const float* h0       = (const float*)d_in[2];
    const float* embed_W  = (const float*)d_in[4];
    const float* fc_W     = (const float*)d_in[5];
    const float* fc_b     = (const float*)d_in[6];
    const float* bn_gamma = (const float*)d_in[7];
    const float* bn_beta  = (const float*)d_in[8];
    const float* attn_W   = (const float*)d_in[9];
    const float* attn_b   = (const float*)d_in[10];
    const float* comb_W   = (const float*)d_in[11];
    const float* comb_b   = (const float*)d_in[12];
    const float* gru_Wih  = (const float*)d_in[13];
    const float* gru_Whh  = (const float*)d_in[14];
    const float* gru_bih  = (const float*)d_in[15];
    const float* gru_bhh  = (const float*)d_in[16];
    const float* out_W    = (const float*)d_in[17];
    const float* out_b    = (const float*)d_in[18];

    float* out     = (float*)d_out;
    float* logits  = out;                       // [8192, 10000]
    float* hiddens = out + (size_t)TB*VV;       // [128, 64, 512]

    zero_init<<<128,256>>>();
    cvt_w<<<2048,256>>>(out_W);
    fc_kernel<<<128,256>>>(features, fc_W, fc_b);
    bn_kernel<<<1,512>>>(bn_gamma, bn_beta);
    prep_kernel<<<1024,256>>>(captions, embed_W, h0);
    for (int t=0;t<TT;t++){
        step_k1<<<160,256>>>(attn_W, attn_b, gru_Whh, gru_bhh, t);
        step_softmax<<<128,256>>>();
        step_k2<<<64,256>>>(comb_W, comb_b, t);
        step_k3a<<<96,256>>>(gru_Wih, gru_bih);
        step_k3b<<<256,256>>>(hiddens, t);
    }
    cvt_pk<<<2048,256>>>();
    out_gemm_mma<<<dim3(NT,64),256>>>(out_b, logits);
    lsm_kernel<<<TB,256>>>(logits);
}

// round 11
// speedup vs baseline: 2.0741x; 2.0741x over previous
#include <cuda_runtime.h>
#include <cuda_bf16.h>
#include <math.h>
#include <stdint.h>

#define BB 128
#define TT 64
#define EE 512
#define HH 512
#define VV 10000
#define FIN 2048
#define TB (TT*BB)
#define NT 79
#define GRID_R 148
#define SMEM_TILE ((128+64)*132*4)

__device__ float g_f[BB*EE];
__device__ float g_feats[BB*EE];
__device__ float g_x[TT*BB*EE];
__device__ float g_h[BB*HH];
__device__ float g_aw[BB*HH];                 // applied = feats * attn weights
__device__ float g_Ax[(size_t)TB*512];
__device__ float g_Gx[(size_t)TB*1536];
__device__ float g_Wf[1536*1024];
__device__ float g_gb[1536];
__device__ float g_sp_al[4*BB*512];
__device__ float g_sp_gh[4*BB*1536];
__device__ float g_sp_gx[4*BB*1536];
__device__ __nv_bfloat16 g_pk16[TB*512];
__device__ __nv_bfloat16 g_w16[NT*128*512];
__device__ unsigned g_cnt;

__device__ __forceinline__ float4 ld4(const float* p){ return *(const float4*)p; }
__device__ __forceinline__ uint32_t smem_u32(const void* p){
    uint32_t a;
    asm("{ .reg .u64 t; cvta.to.shared.u64 t, %1; cvt.u32.u64 %0, t; }" : "=r"(a) : "l"(p));
    return a;
}
__device__ __forceinline__ void ldm4(uint32_t* r, uint32_t addr){
    asm volatile("ldmatrix.sync.aligned.m8n8.x4.shared.b16 {%0,%1,%2,%3}, [%4];"
        : "=r"(r[0]),"=r"(r[1]),"=r"(r[2]),"=r"(r[3]) : "r"(addr));
}
__device__ __forceinline__ void mma16816(float* c, const uint32_t* a, uint32_t b0, uint32_t b1){
    asm volatile("mma.sync.aligned.m16n8k16.row.col.f32.bf16.bf16.f32 "
        "{%0,%1,%2,%3}, {%4,%5,%6,%7}, {%8,%9}, {%0,%1,%2,%3};"
        : "+f"(c[0]),"+f"(c[1]),"+f"(c[2]),"+f"(c[3])
        : "r"(a[0]),"r"(a[1]),"r"(a[2]),"r"(a[3]), "r"(b0),"r"(b1));
}
__device__ __forceinline__ uint32_t f2tf32(float f){
    uint32_t r; asm("cvt.rna.tf32.f32 %0, %1;" : "=r"(r) : "f"(f)); return r;
}
__device__ __forceinline__ void mma_tf32(float* c, const uint32_t* a, uint32_t b0, uint32_t b1){
    asm volatile("mma.sync.aligned.m16n8k8.row.col.f32.tf32.tf32.f32 "
        "{%0,%1,%2,%3}, {%4,%5,%6,%7}, {%8,%9}, {%0,%1,%2,%3};"
        : "+f"(c[0]),"+f"(c[1]),"+f"(c[2]),"+f"(c[3])
        : "r"(a[0]),"r"(a[1]),"r"(a[2]),"r"(a[3]), "r"(b0),"r"(b1));
}

__device__ __forceinline__ void gsync(unsigned target){
    __syncthreads();
    if (threadIdx.x == 0){
        __threadfence();
        atomicAdd(&g_cnt, 1u);
        while (atomicAdd(&g_cnt, 0u) < target) __nanosleep(64);
        __threadfence();
    }
    __syncthreads();
}

// C[128, n0:n0+64] = A[128,K-slice] @ W[n0:n0+64, K-slice]^T (+bias); tf32 MMA.
template<bool ACG>
__device__ void tf32_tile(const float* __restrict__ A, int lda,
                          const float* __restrict__ W, int ldw,
                          float* __restrict__ C, int ldc,
                          int n0, int k0, int nchunk,
                          const float* __restrict__ bias, float* sm)
{
    float (*As)[132] = (float(*)[132])sm;
    float (*Ws)[132] = (float(*)[132])(sm + 128*132);
    const int tid = threadIdx.x, lane = tid & 31, wid = tid >> 5;
    const int wm = wid & 3, wn = wid >> 2;
    const int r0 = lane >> 2, c0 = lane & 3;
    float acc[2][4][4];
    #pragma unroll
    for (int i=0;i<2;i++)
        #pragma unroll
        for (int j=0;j<4;j++)
            #pragma unroll
            for (int q=0;q<4;q++) acc[i][j][q] = 0.f;

    for (int ch = 0; ch < nchunk; ch++){
        int kb = k0 + ch*128;
        #pragma unroll
        for (int i=0;i<16;i++){
            int f4 = tid + i*256;
            int r = f4 >> 5, c4 = f4 & 31;
            const float4* p = (const float4*)(A + (size_t)r*lda + kb + c4*4);
            float4 v = ACG ? __ldcg(p) : *p;
            *(float4*)&As[r][c4*4] = v;
        }
        #pragma unroll
        for (int i=0;i<8;i++){
            int f4 = tid + i*256;
            int r = f4 >> 5, c4 = f4 & 31;
            *(float4*)&Ws[r][c4*4] = *(const float4*)(W + (size_t)(n0 + r)*ldw + kb + c4*4);
        }
        __syncthreads();
        #pragma unroll
        for (int ks=0; ks<16; ks++){
            int kk = ks*8;
            uint32_t af[2][4], bf[4][2];
            #pragma unroll
            for (int mf=0; mf<2; mf++){
                int mr = wm*32 + mf*16;
                af[mf][0] = f2tf32(As[mr + r0     ][kk + c0]);
                af[mf][1] = f2tf32(As[mr + r0 + 8 ][kk + c0]);
                af[mf][2] = f2tf32(As[mr + r0     ][kk + c0 + 4]);
                af[mf][3] = f2tf32(As[mr + r0 + 8 ][kk + c0 + 4]);
            }
            #pragma unroll
            for (int nf=0; nf<4; nf++){
                int nb = wn*32 + nf*8 + r0;
                bf[nf][0] = f2tf32(Ws[nb][kk + c0]);
                bf[nf][1] = f2tf32(Ws[nb][kk + c0 + 4]);
            }
            #pragma unroll
            for (int mf=0; mf<2; mf++)
                #pragma unroll
                for (int nf=0; nf<4; nf++)
                    mma_tf32(acc[mf][nf], af[mf], bf[nf][0], bf[nf][1]);
        }
        __syncthreads();
    }
    #pragma unroll
    for (int mf=0; mf<2; mf++){
        int row = wm*32 + mf*16 + r0;
        #pragma unroll
        for (int nf=0; nf<4; nf++){
            int col = n0 + wn*32 + nf*8 + 2*c0;
            float2 v0, v1;
            v0.x = acc[mf][nf][0]; v0.y = acc[mf][nf][1];
            v1.x = acc[mf][nf][2]; v1.y = acc[mf][nf][3];
            if (bias){
                float b0 = bias[col], b1 = bias[col+1];
                v0.x += b0; v0.y += b1; v1.x += b0; v1.y += b1;
            }
            *(float2*)&C[(size_t)row*ldc + col] = v0;
            *(float2*)&C[(size_t)(row+8)*ldc + col] = v1;
        }
    }
}

// ---------------- setup kernels ----------------
__global__ void zero_init(){
    int i0 = blockIdx.x*blockDim.x + threadIdx.x;
    if (i0 == 0) g_cnt = 0u;
    for (int i=i0;i<BB*EE;i+=gridDim.x*blockDim.x) g_f[i]=0.f;
}

__global__ void cvt_w(const float* __restrict__ outW){
    int stride = gridDim.x*blockDim.x;
    for (int i = blockIdx.x*blockDim.x + threadIdx.x; i < NT*128*512; i += stride){
        int r = i >> 9;
        g_w16[i] = __float2bfloat16(r < VV ? outW[i] : 0.f);
    }
}

// g_Wf[1536,1024] = Wih[1536,512] @ comb_W[512,1024]   (fp32)
__global__ void fold_kernel(const float* __restrict__ wih, const float* __restrict__ combW){
    __shared__ float As[32][132];
    __shared__ float Bs[32][68];
    int m0 = blockIdx.y * 128, n0 = blockIdx.x * 64;
    int tid = threadIdx.x, cx = tid & 15, ry = tid >> 4;
    float acc[8][4];
    for (int i=0;i<8;i++)
        for (int j=0;j<4;j++) acc[i][j]=0.f;
    for (int k0=0;k0<512;k0+=32){
        #pragma unroll
        for (int i=0;i<4;i++){
            int idx = tid + i*256;
            int m = idx >> 3, q = idx & 7;
            float4 v = ld4(&wih[(m0+m)*512 + k0 + 4*q]);
            As[4*q+0][m]=v.x; As[4*q+1][m]=v.y; As[4*q+2][m]=v.z; As[4*q+3][m]=v.w;
        }
        #pragma unroll
        for (int i=0;i<2;i++){
            int f4 = tid + i*256;
            int k = f4 >> 4, n4 = f4 & 15;
            *(float4*)&Bs[k][n4*4] = ld4(&combW[(k0+k)*1024 + n0 + n4*4]);
        }
        __syncthreads();
        #pragma unroll
        for (int k=0;k<32;k++){
            float4 a0=ld4(&As[k][8*ry]), a1=ld4(&As[k][8*ry+4]);
            float4 w=ld4(&Bs[k][4*cx]);
            float av[8]={a0.x,a0.y,a0.z,a0.w,a1.x,a1.y,a1.z,a1.w};
            float wv[4]={w.x,w.y,w.z,w.w};
            #pragma unroll
            for(int i=0;i<8;i++)
              #pragma unroll
              for(int j=0;j<4;j++)
                acc[i][j] = fmaf(av[i], wv[j], acc[i][j]);
        }
        __syncthreads();
    }
    #pragma unroll
    for(int i=0;i<8;i++)
        #pragma unroll
        for(int j=0;j<4;j++)
            g_Wf[(size_t)(m0+8*ry+i)*1024 + n0+4*cx+j] = acc[i][j];
}

__global__ void gb_kernel(const float* __restrict__ wih, const float* __restrict__ bih,
                          const float* __restrict__ comb_b){
    int a = blockIdx.x*256 + threadIdx.x;
    if (a < 1536){
        float s = bih[a];
        for (int c=0;c<512;c++) s += comb_b[c]*wih[a*512+c];
        g_gb[a] = s;
    }
}

__global__ void fc_kernel(const float* __restrict__ features,
                          const float* __restrict__ fcW, const float* __restrict__ fcb){
    __shared__ float As[32][132]; __shared__ float Ws[32][68];
    int tile = blockIdx.x & 7, split = blockIdx.x >> 3;
    int tid = threadIdx.x, cx = tid & 15, ry = tid >> 4;
    int n0 = tile*64, kBeg = split*128;
    float acc[8][4];
    for (int i=0;i<8;i++)
        for (int j=0;j<4;j++) acc[i][j]=0.f;
    for (int k0 = kBeg; k0 < kBeg+128; k0 += 32) {
        #pragma unroll
        for (int i=0;i<4;i++){
            int idx = tid + i*256;
            int m = idx >> 3, q = idx & 7;
            float4 v = ld4(&features[m*FIN + k0 + 4*q]);
            As[4*q+0][m]=v.x; As[4*q+1][m]=v.y; As[4*q+2][m]=v.z; As[4*q+3][m]=v.w;
        }
        #pragma unroll
        for (int i=0;i<2;i++){
            int idx = tid + i*256;
            int n = idx >> 3, q = idx & 7;
            float4 v = ld4(&fcW[(n0+n)*FIN + k0 + 4*q]);
            Ws[4*q+0][n]=v.x; Ws[4*q+1][n]=v.y; Ws[4*q+2][n]=v.z; Ws[4*q+3][n]=v.w;
        }
        __syncthreads();
        #pragma unroll
        for (int k=0;k<32;k++){
            float4 a0 = ld4(&As[k][8*ry]);
            float4 a1 = ld4(&As[k][8*ry+4]);
            float4 w  = ld4(&Ws[k][4*cx]);
            float av[8] = {a0.x,a0.y,a0.z,a0.w,a1.x,a1.y,a1.z,a1.w};
            float wv[4] = {w.x,w.y,w.z,w.w};
            #pragma unroll
            for(int i=0;i<8;i++)
              #pragma unroll
              for(int j=0;j<4;j++)
                acc[i][j] = fmaf(av[i], wv[j], acc[i][j]);
        }
        __syncthreads();
    }
    #pragma unroll
    for(int i=0;i<8;i++){
        int m = 8*ry + i;
        #pragma unroll
        for(int j=0;j<4;j++){
            int n = n0 + 4*cx + j;
            float v = acc[i][j];
            if (split == 0) v += fcb[n];
            atomicAdd(&g_f[m*EE + n], v);
        }
    }
}

__global__ void bn_kernel(const float* __restrict__ gamma, const float* __restrict__ beta){
    __shared__ float s1[16][17], s2[16][17];
    int jc = threadIdx.x & 15, rg = threadIdx.x >> 4;
    int j = blockIdx.x*16 + jc;
    float sum=0.f, sq=0.f;
    for (int i=0;i<8;i++){
        float v = g_f[(rg*8+i)*512 + j];
        sum += v; sq += v*v;
    }
    s1[jc][rg]=sum; s2[jc][rg]=sq;
    __syncthreads();
    if (rg == 0){
        float a=0.f,bq=0.f;
        for (int i=0;i<16;i++){ a+=s1[jc][i]; bq+=s2[jc][i]; }
        float mu = a*(1.f/128.f);
        s1[jc][16]=mu; s2[jc][16]=rsqrtf(bq*(1.f/128.f)-mu*mu+1e-5f);
    }
    __syncthreads();
    float mu=s1[jc][16], rstd=s2[jc][16];
    float ga=gamma[j], be=beta[j];
    for (int i=0;i<8;i++){
        int idx=(rg*8+i)*512 + j;
        g_feats[idx] = ga*(g_f[idx]-mu)*rstd + be;
    }
}

__global__ void prep_kernel(const int* __restrict__ captions,
                            const float* __restrict__ embed_W,
                            const float* __restrict__ h0){
    int stride = gridDim.x*blockDim.x;
    for (int gi = blockIdx.x*blockDim.x + threadIdx.x; gi < TT*BB*EE; gi += stride){
        int t = gi >> 16, idx = gi & 65535;
        int b = idx >> 9, e = idx & 511;
        float v;
        if (t == 0) v = g_feats[idx];
        else { int cap = captions[b*TT + (t-1)]; v = embed_W[cap*EE + e]; }
        g_x[gi] = v;
    }
    for (int i = blockIdx.x*blockDim.x + threadIdx.x; i < BB*HH; i += stride)
        g_h[i] = h0[i];
}

// ---------------- bulk tf32 precompute ----------------
__global__ void bulk_ax(const float* __restrict__ attn_W, const float* __restrict__ attn_b){
    extern __shared__ float sm[];
    tf32_tile<false>(g_x + (size_t)blockIdx.y*128*512, 512, attn_W, 1024,
                     g_Ax + (size_t)blockIdx.y*128*512, 512, blockIdx.x*64, 0, 4, attn_b, sm);
}
__global__ void bulk_gx(){
    extern __shared__ float sm[];
    tf32_tile<false>(g_x + (size_t)blockIdx.y*128*512, 512, g_Wf, 1024,
                     g_Gx + (size_t)blockIdx.y*128*1536, 1536, blockIdx.x*64, 0, 4, g_gb, sm);
}

// ---------------- persistent recurrence ----------------
__global__ __launch_bounds__(256,1) void recur_kernel(const float* __restrict__ attn_W,
                                                      const float* __restrict__ whh,
                                                      const float* __restrict__ bhh,
                                                      float* __restrict__ out_hidden){
    extern __shared__ float sm[];
    __shared__ float red[256];
    const int bid = blockIdx.x, tid = threadIdx.x;
    unsigned target = 0;

    for (int t = 0; t < TT; t++){
        // P1: al partials (h @ attn_W[:,512:]^T) + gh partials (h @ Whh^T)
        if (bid < 32){
            int tile = bid >> 2, sp = bid & 3;
            tf32_tile<true>(g_h, 512, attn_W + 512, 1024,
                            g_sp_al + sp*BB*512, 512, tile*64, sp*128, 1, nullptr, sm);
        } else if (bid < 128){
            int q = bid - 32, tile = q >> 2, sp = q & 3;
            tf32_tile<true>(g_h, 512, whh, 512,
                            g_sp_gh + sp*BB*1536, 1536, tile*64, sp*128, 1, nullptr, sm);
        }
        target += GRID_R; gsync(target);

        // P2: softmax + applied
        if (bid < 128){
            int b = bid;
            const float* ax = g_Ax + ((size_t)t*128 + b)*512;
            float v0 = ax[tid], v1 = ax[tid+256];
            #pragma unroll
            for (int s=0;s<4;s++){
                v0 += __ldcg(&g_sp_al[s*BB*512 + b*512 + tid]);
                v1 += __ldcg(&g_sp_al[s*BB*512 + b*512 + 256 + tid]);
            }
            float m = fmaxf(v0,v1);
            red[tid]=m; __syncthreads();
            for (int s=128;s;s>>=1){ if(tid<s) red[tid]=fmaxf(red[tid],red[tid+s]); __syncthreads(); }
            float mx = red[0]; __syncthreads();
            float e0=expf(v0-mx), e1=expf(v1-mx);
            red[tid]=e0+e1; __syncthreads();
            for (int s=128;s;s>>=1){ if(tid<s) red[tid]+=red[tid+s]; __syncthreads(); }
            float inv = 1.f/red[0];
            g_aw[b*512+tid]     = e0*inv*g_feats[b*512+tid];
            g_aw[b*512+256+tid] = e1*inv*g_feats[b*512+256+tid];
        }
        target += GRID_R; gsync(target);

        // P3: gx partials (applied @ W2^T)
        if (bid < 96){
            int tile = bid >> 2, sp = bid & 3;
            tf32_tile<true>(g_aw, 512, g_Wf + 512, 1024,
                            g_sp_gx + sp*BB*1536, 1536, tile*64, sp*128, 1, nullptr, sm);
        }
        target += GRID_R; gsync(target);

        // P4: GRU combine
        for (int idx = bid*256 + tid; idx < BB*HH; idx += GRID_R*256){
            int b = idx >> 9, j = idx & 511;
            size_t r = (size_t)t*128 + b;
            float xr = g_Gx[r*1536 + j],        hr = bhh[j];
            float xz = g_Gx[r*1536 + j + 512],  hz = bhh[j+512];
            float xn = g_Gx[r*1536 + j + 1024], hn = bhh[j+1024];
            #pragma unroll
            for (int s=0;s<4;s++){
                const float* px = g_sp_gx + s*BB*1536 + b*1536;
                const float* ph = g_sp_gh + s*BB*1536 + b*1536;
                xr += __ldcg(px + j);        hr += __ldcg(ph + j);
                xz += __ldcg(px + j + 512);  hz += __ldcg(ph + j + 512);
                xn += __ldcg(px + j + 1024); hn += __ldcg(ph + j + 1024);
            }
            float hx = g_h[idx];
            float rg = 1.f/(1.f+expf(-(xr+hr)));
            float zg = 1.f/(1.f+expf(-(xz+hz)));
            float nt = tanhf(xn + rg*hn);
            float h = (1.f-zg)*nt + zg*hx;
            g_h[idx] = h;
            out_hidden[(size_t)b*(TT*HH) + t*HH + j] = h;
            g_pk16[r*512 + j] = __float2bfloat16(h);
        }
        target += GRID_R; gsync(target);
    }
}

// ---------------- HMMA bf16 logits GEMM ----------------
#define APAD 72
__global__ __launch_bounds__(256) void out_gemm_mma(const float* __restrict__ outb,
                                                    float* __restrict__ logits){
    __shared__ __nv_bfloat16 Asm[128][APAD];
    __shared__ __nv_bfloat16 Bsm[128][APAD];
    __shared__ float s_bias[128];
    const int tid = threadIdx.x, lane = tid & 31, wid = tid >> 5;
    const int wm = wid & 3, wn = wid >> 2;
    const int m0 = blockIdx.y * 128, n0 = blockIdx.x * 128;
    if (tid < 128){ int n = n0 + tid; s_bias[tid] = (n < VV) ? outb[n] : 0.f; }
    float acc[2][8][4];
    #pragma unroll
    for (int i=0;i<2;i++)
        #pragma unroll
        for (int j=0;j<8;j++)
            #pragma unroll
            for (int q=0;q<4;q++) acc[i][j][q]=0.f;
    const __nv_bfloat16* Ag = g_pk16 + (size_t)m0 * 512;
    const __nv_bfloat16* Bg = g_w16  + (size_t)n0 * 512;
    const int lrow = lane & 15, lkh = (lane >> 4) * 8;
    for (int c = 0; c < 8; c++){
        #pragma unroll
        for (int j = 0; j < 4; j++){
            int idx = tid + j*256;
            int r = idx >> 3, cv = idx & 7;
            *(uint4*)&Asm[r][cv*8] = *(const uint4*)(Ag + (size_t)r*512 + c*64 + cv*8);
            *(uint4*)&Bsm[r][cv*8] = *(const uint4*)(Bg + (size_t)r*512 + c*64 + cv*8);
        }
        __syncthreads();
        #pragma unroll
        for (int ks = 0; ks < 4; ks++){
            int kk = ks*16;
            uint32_t a[2][4];
            #pragma unroll
            for (int mt=0; mt<2; mt++){
                uint32_t ad = smem_u32(&Asm[wm*32 + mt*16 + lrow][kk + lkh]);
                ldm4(a[mt], ad);
            }
            uint32_t b[4][4];
            #pragma unroll
            for (int nt=0; nt<4; nt++){
                uint32_t bd = smem_u32(&Bsm[wn*64 + nt*16 + lrow][kk + lkh]);
                ldm4(b[nt], bd);
            }
            #pragma unroll
            for (int mt=0; mt<2; mt++)
                #pragma unroll
                for (int nt=0; nt<4; nt++){
                    mma16816(acc[mt][nt*2+0], a[mt], b[nt][0], b[nt][2]);
                    mma16816(acc[mt][nt*2+1], a[mt], b[nt][1], b[nt][3]);
                }
        }
        __syncthreads();
    }
    const int r0 = lane >> 2, c2 = (lane & 3) * 2;
    #pragma unroll
    for (int mt=0; mt<2; mt++){
        int row = m0 + wm*32 + mt*16 + r0;
        #pragma unroll
        for (int nt=0; nt<8; nt++){
            int lcol = wn*64 + nt*8 + c2;
            int col  = n0 + lcol;
            if (col < VV){
                float2 v0, v1;
                v0.x = acc[mt][nt][0] + s_bias[lcol];
                v0.y = acc[mt][nt][1] + s_bias[lcol+1];
                v1.x = acc[mt][nt][2] + s_bias[lcol];
                v1.y = acc[mt][nt][3] + s_bias[lcol+1];
                *(float2*)&logits[(size_t)row * VV + col] = v0;
                *(float2*)&logits[(size_t)(row+8) * VV + col] = v1;
            }
        }
    }
}

__global__ void lsm_kernel(float* __restrict__ logits){
    __shared__ float buf[VV];
    __shared__ float red[256];
    int row = blockIdx.x, tid = threadIdx.x;
    float* p = logits + (size_t)row*VV;
    float m = -1e30f;
    for (int j=tid;j<VV;j+=256){ float v = p[j]; buf[j]=v; m = fmaxf(m,v); }
    red[tid]=m; __syncthreads();
    for (int s=128;s;s>>=1){ if(tid<s) red[tid]=fmaxf(red[tid],red[tid+s]); __syncthreads(); }
    float mx = red[0]; __syncthreads();
    float s=0.f;
    for (int j=tid;j<VV;j+=256) s += expf(buf[j]-mx);
    red[tid]=s; __syncthreads();
    for (int st=128;st;st>>=1){ if(tid<st) red[tid]+=red[tid+st]; __syncthreads(); }
    float lse = mx + logf(red[0]);
    for (int j=tid;j<VV;j+=256) p[j] = buf[j]-lse;
}

// ---------------- launch ----------------
extern "C" void kernel_launch(void* const* d_in, const int* in_sizes, int n_in,
                              void* d_out, int out_size){
    const float* features = (const float*)d_in[0];
    const int*   captions = (const int*)  d_in[1];
    const float* h0       = (const float*)d_in[2];
    const float* embed_W  = (const float*)d_in[4];
    const float* fc_W     = (const float*)d_in[5];
    const float* fc_b     = (const float*)d_in[6];
    const float* bn_gamma = (const float*)d_in[7];
    const float* bn_beta  = (const float*)d_in[8];
    const float* attn_W   = (const float*)d_in[9];
    const float* attn_b   = (const float*)d_in[10];
    const float* comb_W   = (const float*)d_in[11];
    const float* comb_b   = (const float*)d_in[12];
    const float* gru_Wih  = (const float*)d_in[13];
    const float* gru_Whh  = (const float*)d_in[14];
    const float* gru_bih  = (const float*)d_in[15];
    const float* gru_bhh  = (const float*)d_in[16];
    const float* out_W    = (const float*)d_in[17];
    const float* out_b    = (const float*)d_in[18];

    float* out     = (float*)d_out;
    float* logits  = out;
    float* hiddens = out + (size_t)TB*VV;

    static bool attr_set = false;
    if (!attr_set){
        cudaFuncSetAttribute(bulk_ax, cudaFuncAttributeMaxDynamicSharedMemorySize, SMEM_TILE);
        cudaFuncSetAttribute(bulk_gx, cudaFuncAttributeMaxDynamicSharedMemorySize, SMEM_TILE);
        cudaFuncSetAttribute(recur_kernel, cudaFuncAttributeMaxDynamicSharedMemorySize, SMEM_TILE);
        attr_set = true;
    }

    zero_init<<<128,256>>>();
    cvt_w<<<2048,256>>>(out_W);
    fold_kernel<<<dim3(16,12),256>>>(gru_Wih, comb_W);
    gb_kernel<<<6,256>>>(gru_Wih, gru_bih, comb_b);
    fc_kernel<<<128,256>>>(features, fc_W, fc_b);
    bn_kernel<<<32,256>>>(bn_gamma, bn_beta);
    prep_kernel<<<1024,256>>>(captions, embed_W, h0);
    bulk_ax<<<dim3(8,64),256,SMEM_TILE>>>(attn_W, attn_b);
    bulk_gx<<<dim3(24,64),256,SMEM_TILE>>>();
    recur_kernel<<<GRID_R,256,SMEM_TILE>>>(attn_W, gru_Whh, gru_bhh, hiddens);
    out_gemm_mma<<<dim3(NT,64),256>>>(out_b, logits);
    lsm_kernel<<<TB,256>>>(logits);
}

// round 13
// speedup vs baseline: 2.2434x; 1.0816x over previous
#include <cuda_runtime.h>
#include <cuda_bf16.h>
#include <math.h>
#include <stdint.h>

#define BB 128
#define TT 64
#define EE 512
#define HH 512
#define VV 10000
#define FIN 2048
#define TB (TT*BB)
#define NT 79
#define GRID_R 148
#define SMEM_TILE ((128+64)*132*4)
#define APAD 72
#define OG_SMEM (4*128*APAD*2)   /* 2 stages x (A+B) x 128 x 72 bf16 = 73728 B */

__device__ float g_f[BB*EE];
__device__ float g_feats[BB*EE];
__device__ float g_x[TT*BB*EE];
__device__ float g_h[BB*HH];
__device__ float g_aw[BB*HH];
__device__ float g_Ax[(size_t)TB*512];
__device__ float g_Gx[(size_t)TB*1536];
__device__ float g_Wf[1536*1024];
__device__ float g_gb[1536];
__device__ float g_sp_al[4*BB*512];
__device__ float g_sp_gh[4*BB*1536];
__device__ float g_sp_gx[4*BB*1536];
__device__ __nv_bfloat16 g_pk16[TB*512];
__device__ __nv_bfloat16 g_w16[NT*128*512];
__device__ unsigned g_cnt;

__device__ __forceinline__ float4 ld4(const float* p){ return *(const float4*)p; }
__device__ __forceinline__ uint32_t smem_u32(const void* p){
    uint32_t a;
    asm("{ .reg .u64 t; cvta.to.shared.u64 t, %1; cvt.u32.u64 %0, t; }" : "=r"(a) : "l"(p));
    return a;
}
__device__ __forceinline__ void ldm4(uint32_t* r, uint32_t addr){
    asm volatile("ldmatrix.sync.aligned.m8n8.x4.shared.b16 {%0,%1,%2,%3}, [%4];"
        : "=r"(r[0]),"=r"(r[1]),"=r"(r[2]),"=r"(r[3]) : "r"(addr));
}
__device__ __forceinline__ void mma16816(float* c, const uint32_t* a, uint32_t b0, uint32_t b1){
    asm volatile("mma.sync.aligned.m16n8k16.row.col.f32.bf16.bf16.f32 "
        "{%0,%1,%2,%3}, {%4,%5,%6,%7}, {%8,%9}, {%0,%1,%2,%3};"
        : "+f"(c[0]),"+f"(c[1]),"+f"(c[2]),"+f"(c[3])
        : "r"(a[0]),"r"(a[1]),"r"(a[2]),"r"(a[3]), "r"(b0),"r"(b1));
}
__device__ __forceinline__ uint32_t f2tf32(float f){
    uint32_t r; asm("cvt.rna.tf32.f32 %0, %1;" : "=r"(r) : "f"(f)); return r;
}
__device__ __forceinline__ void mma_tf32(float* c, const uint32_t* a, uint32_t b0, uint32_t b1){
    asm volatile("mma.sync.aligned.m16n8k8.row.col.f32.tf32.tf32.f32 "
        "{%0,%1,%2,%3}, {%4,%5,%6,%7}, {%8,%9}, {%0,%1,%2,%3};"
        : "+f"(c[0]),"+f"(c[1]),"+f"(c[2]),"+f"(c[3])
        : "r"(a[0]),"r"(a[1]),"r"(a[2]),"r"(a[3]), "r"(b0),"r"(b1));
}
__device__ __forceinline__ void cpasync16(uint32_t dst, const void* src){
    asm volatile("cp.async.cg.shared.global [%0], [%1], 16;" :: "r"(dst), "l"(src) : "memory");
}

__device__ __forceinline__ void gsync(unsigned target){
    __syncthreads();
    if (threadIdx.x == 0){
        __threadfence();
        atomicAdd(&g_cnt, 1u);
        unsigned v;
        do {
            asm volatile("ld.global.cg.u32 %0, [%1];" : "=r"(v) : "l"(&g_cnt) : "memory");
            if (v >= target) break;
            __nanosleep(32);
        } while (1);
        __threadfence();
    }
    __syncthreads();
}

// C[128, n0:n0+64] = A[128,Kslice] @ W[n0:n0+64, Kslice]^T (+bias); tf32 MMA.
// smem holds pre-converted tf32 bits.
template<bool ACG>
__device__ void tf32_tile(const float* __restrict__ A, int lda,
                          const float* __restrict__ W, int ldw,
                          float* __restrict__ C, int ldc,
                          int n0, int k0, int nchunk,
                          const float* __restrict__ bias, float* sm)
{
    uint32_t (*As)[132] = (uint32_t(*)[132])sm;
    uint32_t (*Ws)[132] = (uint32_t(*)[132])(sm + 128*132);
    const int tid = threadIdx.x, lane = tid & 31, wid = tid >> 5;
    const int wm = wid & 3, wn = wid >> 2;
    const int r0 = lane >> 2, c0 = lane & 3;
    float acc[2][4][4];
    #pragma unroll
    for (int i=0;i<2;i++)
        #pragma unroll
        for (int j=0;j<4;j++)
            #pragma unroll
            for (int q=0;q<4;q++) acc[i][j][q] = 0.f;

    for (int ch = 0; ch < nchunk; ch++){
        int kb = k0 + ch*128;
        #pragma unroll
        for (int i=0;i<16;i++){
            int f4 = tid + i*256;
            int r = f4 >> 5, c4 = f4 & 31;
            const float4* p = (const float4*)(A + (size_t)r*lda + kb + c4*4);
            float4 v = ACG ? __ldcg(p) : *p;
            uint4 u; u.x=f2tf32(v.x); u.y=f2tf32(v.y); u.z=f2tf32(v.z); u.w=f2tf32(v.w);
            *(uint4*)&As[r][c4*4] = u;
        }
        #pragma unroll
        for (int i=0;i<8;i++){
            int f4 = tid + i*256;
            int r = f4 >> 5, c4 = f4 & 31;
            float4 v = *(const float4*)(W + (size_t)(n0 + r)*ldw + kb + c4*4);
            uint4 u; u.x=f2tf32(v.x); u.y=f2tf32(v.y); u.z=f2tf32(v.z); u.w=f2tf32(v.w);
            *(uint4*)&Ws[r][c4*4] = u;
        }
        __syncthreads();
        #pragma unroll
        for (int ks=0; ks<16; ks++){
            int kk = ks*8;
            uint32_t af[2][4], bf[4][2];
            #pragma unroll
            for (int mf=0; mf<2; mf++){
                int mr = wm*32 + mf*16;
                af[mf][0] = As[mr + r0     ][kk + c0];
                af[mf][1] = As[mr + r0 + 8 ][kk + c0];
                af[mf][2] = As[mr + r0     ][kk + c0 + 4];
                af[mf][3] = As[mr + r0 + 8 ][kk + c0 + 4];
            }
            #pragma unroll
            for (int nf=0; nf<4; nf++){
                int nb = wn*32 + nf*8 + r0;
                bf[nf][0] = Ws[nb][kk + c0];
                bf[nf][1] = Ws[nb][kk + c0 + 4];
            }
            #pragma unroll
            for (int mf=0; mf<2; mf++)
                #pragma unroll
                for (int nf=0; nf<4; nf++)
                    mma_tf32(acc[mf][nf], af[mf], bf[nf][0], bf[nf][1]);
        }
        __syncthreads();
    }
    #pragma unroll
    for (int mf=0; mf<2; mf++){
        int row = wm*32 + mf*16 + r0;
        #pragma unroll
        for (int nf=0; nf<4; nf++){
            int col = n0 + wn*32 + nf*8 + 2*c0;
            float2 v0, v1;
            v0.x = acc[mf][nf][0]; v0.y = acc[mf][nf][1];
            v1.x = acc[mf][nf][2]; v1.y = acc[mf][nf][3];
            if (bias){
                float b0 = bias[col], b1 = bias[col+1];
                v0.x += b0; v0.y += b1; v1.x += b0; v1.y += b1;
            }
            *(float2*)&C[(size_t)row*ldc + col] = v0;
            *(float2*)&C[(size_t)(row+8)*ldc + col] = v1;
        }
    }
}

// ---------------- setup kernels ----------------
__global__ void zero_init(){
    int i0 = blockIdx.x*blockDim.x + threadIdx.x;
    if (i0 == 0) g_cnt = 0u;
    for (int i=i0;i<BB*EE;i+=gridDim.x*blockDim.x) g_f[i]=0.f;
}

__global__ void cvt_w(const float* __restrict__ outW){
    int stride = gridDim.x*blockDim.x;
    for (int i = blockIdx.x*blockDim.x + threadIdx.x; i < NT*128*512; i += stride){
        int r = i >> 9;
        g_w16[i] = __float2bfloat16(r < VV ? outW[i] : 0.f);
    }
}

__global__ void fold_kernel(const float* __restrict__ wih, const float* __restrict__ combW){
    __shared__ float As[32][132];
    __shared__ float Bs[32][68];
    int m0 = blockIdx.y * 128, n0 = blockIdx.x * 64;
    int tid = threadIdx.x, cx = tid & 15, ry = tid >> 4;
    float acc[8][4];
    for (int i=0;i<8;i++)
        for (int j=0;j<4;j++) acc[i][j]=0.f;
    for (int k0=0;k0<512;k0+=32){
        #pragma unroll
        for (int i=0;i<4;i++){
            int idx = tid + i*256;
            int m = idx >> 3, q = idx & 7;
            float4 v = ld4(&wih[(m0+m)*512 + k0 + 4*q]);
            As[4*q+0][m]=v.x; As[4*q+1][m]=v.y; As[4*q+2][m]=v.z; As[4*q+3][m]=v.w;
        }
        #pragma unroll
        for (int i=0;i<2;i++){
            int f4 = tid + i*256;
            int k = f4 >> 4, n4 = f4 & 15;
            *(float4*)&Bs[k][n4*4] = ld4(&combW[(k0+k)*1024 + n0 + n4*4]);
        }
        __syncthreads();
        #pragma unroll
        for (int k=0;k<32;k++){
            float4 a0=ld4(&As[k][8*ry]), a1=ld4(&As[k][8*ry+4]);
            float4 w=ld4(&Bs[k][4*cx]);
            float av[8]={a0.x,a0.y,a0.z,a0.w,a1.x,a1.y,a1.z,a1.w};
            float wv[4]={w.x,w.y,w.z,w.w};
            #pragma unroll
            for(int i=0;i<8;i++)
              #pragma unroll
              for(int j=0;j<4;j++)
                acc[i][j] = fmaf(av[i], wv[j], acc[i][j]);
        }
        __syncthreads();
    }
    #pragma unroll
    for(int i=0;i<8;i++)
        #pragma unroll
        for(int j=0;j<4;j++)
            g_Wf[(size_t)(m0+8*ry+i)*1024 + n0+4*cx+j] = acc[i][j];
}

__global__ void gb_kernel(const float* __restrict__ wih, const float* __restrict__ bih,
                          const float* __restrict__ comb_b){
    int a = blockIdx.x*8 + (threadIdx.x >> 5);
    int lane = threadIdx.x & 31;
    float s = 0.f;
    for (int c = lane; c < 512; c += 32) s += comb_b[c]*wih[(size_t)a*512 + c];
    #pragma unroll
    for (int o=16;o;o>>=1) s += __shfl_xor_sync(0xFFFFFFFFu, s, o);
    if (lane == 0) g_gb[a] = s + bih[a];
}

__global__ void fc_kernel(const float* __restrict__ features,
                          const float* __restrict__ fcW, const float* __restrict__ fcb){
    __shared__ float As[32][132]; __shared__ float Ws[32][68];
    int tile = blockIdx.x & 7, split = blockIdx.x >> 3;
    int tid = threadIdx.x, cx = tid & 15, ry = tid >> 4;
    int n0 = tile*64, kBeg = split*128;
    float acc[8][4];
    for (int i=0;i<8;i++)
        for (int j=0;j<4;j++) acc[i][j]=0.f;
    for (int k0 = kBeg; k0 < kBeg+128; k0 += 32) {
        #pragma unroll
        for (int i=0;i<4;i++){
            int idx = tid + i*256;
            int m = idx >> 3, q = idx & 7;
            float4 v = ld4(&features[m*FIN + k0 + 4*q]);
            As[4*q+0][m]=v.x; As[4*q+1][m]=v.y; As[4*q+2][m]=v.z; As[4*q+3][m]=v.w;
        }
        #pragma unroll
        for (int i=0;i<2;i++){
            int idx = tid + i*256;
            int n = idx >> 3, q = idx & 7;
            float4 v = ld4(&fcW[(n0+n)*FIN + k0 + 4*q]);
            Ws[4*q+0][n]=v.x; Ws[4*q+1][n]=v.y; Ws[4*q+2][n]=v.z; Ws[4*q+3][n]=v.w;
        }
        __syncthreads();
        #pragma unroll
        for (int k=0;k<32;k++){
            float4 a0 = ld4(&As[k][8*ry]);
            float4 a1 = ld4(&As[k][8*ry+4]);
            float4 w  = ld4(&Ws[k][4*cx]);
            float av[8] = {a0.x,a0.y,a0.z,a0.w,a1.x,a1.y,a1.z,a1.w};
            float wv[4] = {w.x,w.y,w.z,w.w};
            #pragma unroll
            for(int i=0;i<8;i++)
              #pragma unroll
              for(int j=0;j<4;j++)
                acc[i][j] = fmaf(av[i], wv[j], acc[i][j]);
        }
        __syncthreads();
    }
    #pragma unroll
    for(int i=0;i<8;i++){
        int m = 8*ry + i;
        #pragma unroll
        for(int j=0;j<4;j++){
            int n = n0 + 4*cx + j;
            float v = acc[i][j];
            if (split == 0) v += fcb[n];
            atomicAdd(&g_f[m*EE + n], v);
        }
    }
}

__global__ void bn_kernel(const float* __restrict__ gamma, const float* __restrict__ beta){
    __shared__ float s1[16][17], s2[16][17];
    int jc = threadIdx.x & 15, rg = threadIdx.x >> 4;
    int j = blockIdx.x*16 + jc;
    float sum=0.f, sq=0.f;
    for (int i=0;i<8;i++){
        float v = g_f[(rg*8+i)*512 + j];
        sum += v; sq += v*v;
    }
    s1[jc][rg]=sum; s2[jc][rg]=sq;
    __syncthreads();
    if (rg == 0){
        float a=0.f,bq=0.f;
        for (int i=0;i<16;i++){ a+=s1[jc][i]; bq+=s2[jc][i]; }
        float mu = a*(1.f/128.f);
        s1[jc][16]=mu; s2[jc][16]=rsqrtf(bq*(1.f/128.f)-mu*mu+1e-5f);
    }
    __syncthreads();
    float mu=s1[jc][16], rstd=s2[jc][16];
    float ga=gamma[j], be=beta[j];
    for (int i=0;i<8;i++){
        int idx=(rg*8+i)*512 + j;
        g_feats[idx] = ga*(g_f[idx]-mu)*rstd + be;
    }
}

__global__ void prep_kernel(const int* __restrict__ captions,
                            const float* __restrict__ embed_W,
                            const float* __restrict__ h0){
    int stride = gridDim.x*blockDim.x;
    for (int gi = blockIdx.x*blockDim.x + threadIdx.x; gi < TT*BB*EE; gi += stride){
        int t = gi >> 16, idx = gi & 65535;
        int b = idx >> 9, e = idx & 511;
        float v;
        if (t == 0) v = g_feats[idx];
        else { int cap = captions[b*TT + (t-1)]; v = embed_W[cap*EE + e]; }
        g_x[gi] = v;
    }
    for (int i = blockIdx.x*blockDim.x + threadIdx.x; i < BB*HH; i += stride)
        g_h[i] = h0[i];
}

// ---------------- bulk tf32 precompute ----------------
__global__ void bulk_ax(const float* __restrict__ attn_W, const float* __restrict__ attn_b){
    extern __shared__ float sm[];
    tf32_tile<false>(g_x + (size_t)blockIdx.y*128*512, 512, attn_W, 1024,
                     g_Ax + (size_t)blockIdx.y*128*512, 512, blockIdx.x*64, 0, 4, attn_b, sm);
}
__global__ void bulk_gx(){
    extern __shared__ float sm[];
    tf32_tile<false>(g_x + (size_t)blockIdx.y*128*512, 512, g_Wf, 1024,
                     g_Gx + (size_t)blockIdx.y*128*1536, 1536, blockIdx.x*64, 0, 4, g_gb, sm);
}

// ---------------- persistent recurrence ----------------
__global__ __launch_bounds__(256,1) void recur_kernel(const float* __restrict__ attn_W,
                                                      const float* __restrict__ whh,
                                                      const float* __restrict__ bhh,
                                                      float* __restrict__ out_hidden){
    extern __shared__ float sm[];
    __shared__ float red[256];
    const int bid = blockIdx.x, tid = threadIdx.x;
    unsigned target = 0;

    for (int t = 0; t < TT; t++){
        if (bid < 32){
            int tile = bid >> 2, sp = bid & 3;
            tf32_tile<true>(g_h, 512, attn_W + 512, 1024,
                            g_sp_al + sp*BB*512, 512, tile*64, sp*128, 1, nullptr, sm);
        } else if (bid < 128){
            int q = bid - 32, tile = q >> 2, sp = q & 3;
            tf32_tile<true>(g_h, 512, whh, 512,
                            g_sp_gh + sp*BB*1536, 1536, tile*64, sp*128, 1, nullptr, sm);
        }
        target += GRID_R; gsync(target);

        if (bid < 128){
            int b = bid;
            const float* ax = g_Ax + ((size_t)t*128 + b)*512;
            float v0 = ax[tid], v1 = ax[tid+256];
            #pragma unroll
            for (int s=0;s<4;s++){
                v0 += __ldcg(&g_sp_al[s*BB*512 + b*512 + tid]);
                v1 += __ldcg(&g_sp_al[s*BB*512 + b*512 + 256 + tid]);
            }
            float m = fmaxf(v0,v1);
            red[tid]=m; __syncthreads();
            for (int s=128;s;s>>=1){ if(tid<s) red[tid]=fmaxf(red[tid],red[tid+s]); __syncthreads(); }
            float mx = red[0]; __syncthreads();
            float e0=expf(v0-mx), e1=expf(v1-mx);
            red[tid]=e0+e1; __syncthreads();
            for (int s=128;s;s>>=1){ if(tid<s) red[tid]+=red[tid+s]; __syncthreads(); }
            float inv = 1.f/red[0];
            g_aw[b*512+tid]     = e0*inv*g_feats[b*512+tid];
            g_aw[b*512+256+tid] = e1*inv*g_feats[b*512+256+tid];
        }
        target += GRID_R; gsync(target);

        if (bid < 96){
            int tile = bid >> 2, sp = bid & 3;
            tf32_tile<true>(g_aw, 512, g_Wf + 512, 1024,
                            g_sp_gx + sp*BB*1536, 1536, tile*64, sp*128, 1, nullptr, sm);
        }
        target += GRID_R; gsync(target);

        for (int idx = bid*256 + tid; idx < BB*HH; idx += GRID_R*256){
            int b = idx >> 9, j = idx & 511;
            size_t r = (size_t)t*128 + b;
            float xr = g_Gx[r*1536 + j],        hr = bhh[j];
            float xz = g_Gx[r*1536 + j + 512],  hz = bhh[j+512];
            float xn = g_Gx[r*1536 + j + 1024], hn = bhh[j+1024];
            #pragma unroll
            for (int s=0;s<4;s++){
                const float* px = g_sp_gx + s*BB*1536 + b*1536;
                const float* ph = g_sp_gh + s*BB*1536 + b*1536;
                xr += __ldcg(px + j);        hr += __ldcg(ph + j);
                xz += __ldcg(px + j + 512);  hz += __ldcg(ph + j + 512);
                xn += __ldcg(px + j + 1024); hn += __ldcg(ph + j + 1024);
            }
            float hx = g_h[idx];
            float rg = 1.f/(1.f+expf(-(xr+hr)));
            float zg = 1.f/(1.f+expf(-(xz+hz)));
            float nt = tanhf(xn + rg*hn);
            float h = (1.f-zg)*nt + zg*hx;
            g_h[idx] = h;
            out_hidden[(size_t)b*(TT*HH) + t*HH + j] = h;
            g_pk16[r*512 + j] = __float2bfloat16(h);
        }
        target += GRID_R; gsync(target);
    }
}

// ---------------- HMMA bf16 logits GEMM (double-buffered cp.async) ----------------
__global__ __launch_bounds__(256) void out_gemm_mma(const float* __restrict__ outb,
                                                    float* __restrict__ logits){
    extern __shared__ __nv_bfloat16 sm16[];
    __shared__ float s_bias[128];
    const int tid = threadIdx.x, lane = tid & 31, wid = tid >> 5;
    const int wm = wid & 3, wn = wid >> 2;
    const int m0 = blockIdx.y * 128, n0 = blockIdx.x * 128;
    if (tid < 128){ int n = n0 + tid; s_bias[tid] = (n < VV) ? outb[n] : 0.f; }

    __nv_bfloat16* Abase = sm16;                 // [2][128][APAD]
    __nv_bfloat16* Bbase = sm16 + 2*128*APAD;

    float acc[2][8][4];
    #pragma unroll
    for (int i=0;i<2;i++)
        #pragma unroll
        for (int j=0;j<8;j++)
            #pragma unroll
            for (int q=0;q<4;q++) acc[i][j][q]=0.f;

    const __nv_bfloat16* Ag = g_pk16 + (size_t)m0 * 512;
    const __nv_bfloat16* Bg = g_w16  + (size_t)n0 * 512;
    const int lrow = lane & 15, lkh = (lane >> 4) * 8;

    #pragma unroll
    for (int j = 0; j < 4; j++){
        int idx = tid + j*256;
        int r = idx >> 3, cv = idx & 7;
        cpasync16(smem_u32(Abase + r*APAD + cv*8), Ag + (size_t)r*512 + cv*8);
        cpasync16(smem_u32(Bbase + r*APAD + cv*8), Bg + (size_t)r*512 + cv*8);
    }
    asm volatile("cp.async.commit_group;" ::: "memory");

    for (int c = 0; c < 8; c++){
        int cur = c & 1, nxt = cur ^ 1;
        if (c + 1 < 8){
            const __nv_bfloat16* An = Ag + (c+1)*64;
            const __nv_bfloat16* Bn = Bg + (c+1)*64;
            __nv_bfloat16* Ad = Abase + nxt*128*APAD;
            __nv_bfloat16* Bd = Bbase + nxt*128*APAD;
            #pragma unroll
            for (int j = 0; j < 4; j++){
                int idx = tid + j*256;
                int r = idx >> 3, cv = idx & 7;
                cpasync16(smem_u32(Ad + r*APAD + cv*8), An + (size_t)r*512 + cv*8);
                cpasync16(smem_u32(Bd + r*APAD + cv*8), Bn + (size_t)r*512 + cv*8);
            }
            asm volatile("cp.async.commit_group;" ::: "memory");
            asm volatile("cp.async.wait_group 1;" ::: "memory");
        } else {
            asm volatile("cp.async.wait_group 0;" ::: "memory");
        }
        __syncthreads();
        const __nv_bfloat16* Ac = Abase + cur*128*APAD;
        const __nv_bfloat16* Bc = Bbase + cur*128*APAD;
        #pragma unroll
        for (int ks = 0; ks < 4; ks++){
            int kk = ks*16;
            uint32_t a[2][4];
            #pragma unroll
            for (int mt=0; mt<2; mt++){
                uint32_t ad = smem_u32(Ac + (wm*32 + mt*16 + lrow)*APAD + kk + lkh);
                ldm4(a[mt], ad);
            }
            uint32_t b[4][4];
            #pragma unroll
            for (int nt=0; nt<4; nt++){
                uint32_t bd = smem_u32(Bc + (wn*64 + nt*16 + lrow)*APAD + kk + lkh);
                ldm4(b[nt], bd);
            }
            #pragma unroll
            for (int mt=0; mt<2; mt++)
                #pragma unroll
                for (int nt=0; nt<4; nt++){
                    mma16816(acc[mt][nt*2+0], a[mt], b[nt][0], b[nt][2]);
                    mma16816(acc[mt][nt*2+1], a[mt], b[nt][1], b[nt][3]);
                }
        }
        __syncthreads();
    }
    const int r0 = lane >> 2, c2 = (lane & 3) * 2;
    #pragma unroll
    for (int mt=0; mt<2; mt++){
        int row = m0 + wm*32 + mt*16 + r0;
        #pragma unroll
        for (int nt=0; nt<8; nt++){
            int lcol = wn*64 + nt*8 + c2;
            int col  = n0 + lcol;
            if (col < VV){
                float2 v0, v1;
                v0.x = acc[mt][nt][0] + s_bias[lcol];
                v0.y = acc[mt][nt][1] + s_bias[lcol+1];
                v1.x = acc[mt][nt][2] + s_bias[lcol];
                v1.y = acc[mt][nt][3] + s_bias[lcol+1];
                *(float2*)&logits[(size_t)row * VV + col] = v0;
                *(float2*)&logits[(size_t)(row+8) * VV + col] = v1;
            }
        }
    }
}

__global__ void lsm_kernel(float* __restrict__ logits){
    __shared__ float buf[VV];
    __shared__ float red[256];
    int row = blockIdx.x, tid = threadIdx.x;
    float* p = logits + (size_t)row*VV;
    float m = -1e30f;
    for (int j=tid;j<VV;j+=256){ float v = p[j]; buf[j]=v; m = fmaxf(m,v); }
    red[tid]=m; __syncthreads();
    for (int s=128;s;s>>=1){ if(tid<s) red[tid]=fmaxf(red[tid],red[tid+s]); __syncthreads(); }
    float mx = red[0]; __syncthreads();
    float s=0.f;
    for (int j=tid;j<VV;j+=256) s += expf(buf[j]-mx);
    red[tid]=s; __syncthreads();
    for (int st=128;st;st>>=1){ if(tid<st) red[tid]+=red[tid+st]; __syncthreads(); }
    float lse = mx + logf(red[0]);
    for (int j=tid;j<VV;j+=256) p[j] = buf[j]-lse;
}

// ---------------- launch ----------------
extern "C" void kernel_launch(void* const* d_in, const int* in_sizes, int n_in,
                              void* d_out, int out_size){
    const float* features = (const float*)d_in[0];
    const int*   captions = (const int*)  d_in[1];
    const float* h0       = (const float*)d_in[2];
    const float* embed_W  = (const float*)d_in[4];
    const float* fc_W     = (const float*)d_in[5];
    const float* fc_b     = (const float*)d_in[6];
    const float* bn_gamma = (const float*)d_in[7];
    const float* bn_beta  = (const float*)d_in[8];
    const float* attn_W   = (const float*)d_in[9];
    const float* attn_b   = (const float*)d_in[10];
    const float* comb_W   = (const float*)d_in[11];
    const float* comb_b   = (const float*)d_in[12];
    const float* gru_Wih  = (const float*)d_in[13];
    const float* gru_Whh  = (const float*)d_in[14];
    const float* gru_bih  = (const float*)d_in[15];
    const float* gru_bhh  = (const float*)d_in[16];
    const float* out_W    = (const float*)d_in[17];
    const float* out_b    = (const float*)d_in[18];

    float* out     = (float*)d_out;
    float* logits  = out;
    float* hiddens = out + (size_t)TB*VV;

    static bool attr_set = false;
    if (!attr_set){
        cudaFuncSetAttribute(bulk_ax, cudaFuncAttributeMaxDynamicSharedMemorySize, SMEM_TILE);
        cudaFuncSetAttribute(bulk_gx, cudaFuncAttributeMaxDynamicSharedMemorySize, SMEM_TILE);
        cudaFuncSetAttribute(recur_kernel, cudaFuncAttributeMaxDynamicSharedMemorySize, SMEM_TILE);
        cudaFuncSetAttribute(out_gemm_mma, cudaFuncAttributeMaxDynamicSharedMemorySize, OG_SMEM);
        attr_set = true;
    }

    zero_init<<<128,256>>>();
    cvt_w<<<2048,256>>>(out_W);
    fold_kernel<<<dim3(16,12),256>>>(gru_Wih, comb_W);
    gb_kernel<<<192,256>>>(gru_Wih, gru_bih, comb_b);
    fc_kernel<<<128,256>>>(features, fc_W, fc_b);
    bn_kernel<<<32,256>>>(bn_gamma, bn_beta);
    prep_kernel<<<1024,256>>>(captions, embed_W, h0);
    bulk_ax<<<dim3(8,64),256,SMEM_TILE>>>(attn_W, attn_b);
    bulk_gx<<<dim3(24,64),256,SMEM_TILE>>>();
    recur_kernel<<<GRID_R,256,SMEM_TILE>>>(attn_W, gru_Whh, gru_bhh, hiddens);
    out_gemm_mma<<<dim3(NT,64),256,OG_SMEM>>>(out_b, logits);
    lsm_kernel<<<TB,256>>>(logits);
}

// round 15
// speedup vs baseline: 2.2931x; 1.0222x over previous
#include <cuda_runtime.h>
#include <cuda_bf16.h>
#include <math.h>
#include <stdint.h>

#define BB 128
#define TT 64
#define EE 512
#define HH 512
#define VV 10000
#define FIN 2048
#define TB (TT*BB)
#define NT 79
#define GRID_R 148
#define SMEM_TILE (256*132*4)    /* A(128) + Wc1(64) + Wc2(64) rows x 132 u32 = 135168 B */
#define APAD 72
#define OG_SMEM (4*128*APAD*2)

__device__ float g_f[BB*EE];
__device__ float g_feats[BB*EE];
__device__ float g_x[TT*BB*EE];
__device__ float g_h[BB*HH];
__device__ float g_aw[BB*HH];
__device__ float g_Ax[(size_t)TB*512];
__device__ float g_Gx[(size_t)TB*1536];
__device__ float g_Wf[1536*1024];
__device__ float g_gb[1536];
__device__ float g_sp_al[4*BB*512];
__device__ float g_sp_gh[4*BB*1536];
__device__ float g_sp_gx[4*BB*1536];
__device__ __nv_bfloat16 g_pk16[TB*512];
__device__ __nv_bfloat16 g_w16[NT*128*512];
__device__ unsigned g_cnt;

__device__ __forceinline__ float4 ld4(const float* p){ return *(const float4*)p; }
__device__ __forceinline__ uint32_t smem_u32(const void* p){
    uint32_t a;
    asm("{ .reg .u64 t; cvta.to.shared.u64 t, %1; cvt.u32.u64 %0, t; }" : "=r"(a) : "l"(p));
    return a;
}
__device__ __forceinline__ void ldm4(uint32_t* r, uint32_t addr){
    asm volatile("ldmatrix.sync.aligned.m8n8.x4.shared.b16 {%0,%1,%2,%3}, [%4];"
        : "=r"(r[0]),"=r"(r[1]),"=r"(r[2]),"=r"(r[3]) : "r"(addr));
}
__device__ __forceinline__ void mma16816(float* c, const uint32_t* a, uint32_t b0, uint32_t b1){
    asm volatile("mma.sync.aligned.m16n8k16.row.col.f32.bf16.bf16.f32 "
        "{%0,%1,%2,%3}, {%4,%5,%6,%7}, {%8,%9}, {%0,%1,%2,%3};"
        : "+f"(c[0]),"+f"(c[1]),"+f"(c[2]),"+f"(c[3])
        : "r"(a[0]),"r"(a[1]),"r"(a[2]),"r"(a[3]), "r"(b0),"r"(b1));
}
__device__ __forceinline__ uint32_t f2tf32(float f){
    uint32_t r; asm("cvt.rna.tf32.f32 %0, %1;" : "=r"(r) : "f"(f)); return r;
}
__device__ __forceinline__ void mma_tf32(float* c, const uint32_t* a, uint32_t b0, uint32_t b1){
    asm volatile("mma.sync.aligned.m16n8k8.row.col.f32.tf32.tf32.f32 "
        "{%0,%1,%2,%3}, {%4,%5,%6,%7}, {%8,%9}, {%0,%1,%2,%3};"
        : "+f"(c[0]),"+f"(c[1]),"+f"(c[2]),"+f"(c[3])
        : "r"(a[0]),"r"(a[1]),"r"(a[2]),"r"(a[3]), "r"(b0),"r"(b1));
}
__device__ __forceinline__ void cpasync16(uint32_t dst, const void* src){
    asm volatile("cp.async.cg.shared.global [%0], [%1], 16;" :: "r"(dst), "l"(src) : "memory");
}

__device__ __forceinline__ void gsync(unsigned target){
    __syncthreads();
    if (threadIdx.x == 0){
        __threadfence();
        atomicAdd(&g_cnt, 1u);
        unsigned v;
        do {
            asm volatile("ld.global.cg.u32 %0, [%1];" : "=r"(v) : "l"(&g_cnt) : "memory");
            if (v >= target) break;
            __nanosleep(32);
        } while (1);
        __threadfence();
    }
    __syncthreads();
}

// ---------------- general tf32 tile GEMM (bulk precompute) ----------------
template<bool ACG>
__device__ void tf32_tile(const float* __restrict__ A, int lda,
                          const float* __restrict__ W, int ldw,
                          float* __restrict__ C, int ldc,
                          int n0, int k0, int nchunk,
                          const float* __restrict__ bias, float* sm)
{
    uint32_t (*As)[132] = (uint32_t(*)[132])sm;
    uint32_t (*Ws)[132] = (uint32_t(*)[132])(sm + 128*132);
    const int tid = threadIdx.x, lane = tid & 31, wid = tid >> 5;
    const int wm = wid & 3, wn = wid >> 2;
    const int r0 = lane >> 2, c0 = lane & 3;
    float acc[2][4][4];
    #pragma unroll
    for (int i=0;i<2;i++)
        #pragma unroll
        for (int j=0;j<4;j++)
            #pragma unroll
            for (int q=0;q<4;q++) acc[i][j][q] = 0.f;

    for (int ch = 0; ch < nchunk; ch++){
        int kb = k0 + ch*128;
        #pragma unroll
        for (int i=0;i<16;i++){
            int f4 = tid + i*256;
            int r = f4 >> 5, c4 = f4 & 31;
            const float4* p = (const float4*)(A + (size_t)r*lda + kb + c4*4);
            float4 v = ACG ? __ldcg(p) : *p;
            uint4 u; u.x=f2tf32(v.x); u.y=f2tf32(v.y); u.z=f2tf32(v.z); u.w=f2tf32(v.w);
            *(uint4*)&As[r][c4*4] = u;
        }
        #pragma unroll
        for (int i=0;i<8;i++){
            int f4 = tid + i*256;
            int r = f4 >> 5, c4 = f4 & 31;
            float4 v = *(const float4*)(W + (size_t)(n0 + r)*ldw + kb + c4*4);
            uint4 u; u.x=f2tf32(v.x); u.y=f2tf32(v.y); u.z=f2tf32(v.z); u.w=f2tf32(v.w);
            *(uint4*)&Ws[r][c4*4] = u;
        }
        __syncthreads();
        #pragma unroll
        for (int ks=0; ks<16; ks++){
            int kk = ks*8;
            uint32_t af[2][4], bf[4][2];
            #pragma unroll
            for (int mf=0; mf<2; mf++){
                int mr = wm*32 + mf*16;
                af[mf][0] = As[mr + r0     ][kk + c0];
                af[mf][1] = As[mr + r0 + 8 ][kk + c0];
                af[mf][2] = As[mr + r0     ][kk + c0 + 4];
                af[mf][3] = As[mr + r0 + 8 ][kk + c0 + 4];
            }
            #pragma unroll
            for (int nf=0; nf<4; nf++){
                int nb = wn*32 + nf*8 + r0;
                bf[nf][0] = Ws[nb][kk + c0];
                bf[nf][1] = Ws[nb][kk + c0 + 4];
            }
            #pragma unroll
            for (int mf=0; mf<2; mf++)
                #pragma unroll
                for (int nf=0; nf<4; nf++)
                    mma_tf32(acc[mf][nf], af[mf], bf[nf][0], bf[nf][1]);
        }
        __syncthreads();
    }
    #pragma unroll
    for (int mf=0; mf<2; mf++){
        int row = wm*32 + mf*16 + r0;
        #pragma unroll
        for (int nf=0; nf<4; nf++){
            int col = n0 + wn*32 + nf*8 + 2*c0;
            float2 v0, v1;
            v0.x = acc[mf][nf][0]; v0.y = acc[mf][nf][1];
            v1.x = acc[mf][nf][2]; v1.y = acc[mf][nf][3];
            if (bias){
                float b0 = bias[col], b1 = bias[col+1];
                v0.x += b0; v0.y += b1; v1.x += b0; v1.y += b1;
            }
            *(float2*)&C[(size_t)row*ldc + col] = v0;
            *(float2*)&C[(size_t)(row+8)*ldc + col] = v1;
        }
    }
}

// ---------------- weight-stationary tile GEMM (recurrence; W pre-cached in smem) ----------------
__device__ void w_preload(const float* __restrict__ W, int ldw, int n0, int k0,
                          uint32_t (*Wc)[132]){
    const int tid = threadIdx.x;
    #pragma unroll
    for (int i=0;i<8;i++){
        int f4 = tid + i*256;
        int r = f4 >> 5, c4 = f4 & 31;
        float4 v = *(const float4*)(W + (size_t)(n0 + r)*ldw + k0 + c4*4);
        uint4 u; u.x=f2tf32(v.x); u.y=f2tf32(v.y); u.z=f2tf32(v.z); u.w=f2tf32(v.w);
        *(uint4*)&Wc[r][c4*4] = u;
    }
}

__device__ void tf32_tile_c(const float* __restrict__ A, int lda,
                            float* __restrict__ C, int ldc,
                            int n0, int k0, float* sm, uint32_t (*Ws)[132])
{
    uint32_t (*As)[132] = (uint32_t(*)[132])sm;
    const int tid = threadIdx.x, lane = tid & 31, wid = tid >> 5;
    const int wm = wid & 3, wn = wid >> 2;
    const int r0 = lane >> 2, c0 = lane & 3;
    float acc[2][4][4];
    #pragma unroll
    for (int i=0;i<2;i++)
        #pragma unroll
        for (int j=0;j<4;j++)
            #pragma unroll
            for (int q=0;q<4;q++) acc[i][j][q] = 0.f;

    #pragma unroll
    for (int i=0;i<16;i++){
        int f4 = tid + i*256;
        int r = f4 >> 5, c4 = f4 & 31;
        float4 v = __ldcg((const float4*)(A + (size_t)r*lda + k0 + c4*4));
        uint4 u; u.x=f2tf32(v.x); u.y=f2tf32(v.y); u.z=f2tf32(v.z); u.w=f2tf32(v.w);
        *(uint4*)&As[r][c4*4] = u;
    }
    __syncthreads();
    #pragma unroll
    for (int ks=0; ks<16; ks++){
        int kk = ks*8;
        uint32_t af[2][4], bf[4][2];
        #pragma unroll
        for (int mf=0; mf<2; mf++){
            int mr = wm*32 + mf*16;
            af[mf][0] = As[mr + r0     ][kk + c0];
            af[mf][1] = As[mr + r0 + 8 ][kk + c0];
            af[mf][2] = As[mr + r0     ][kk + c0 + 4];
            af[mf][3] = As[mr + r0 + 8 ][kk + c0 + 4];
        }
        #pragma unroll
        for (int nf=0; nf<4; nf++){
            int nb = wn*32 + nf*8 + r0;
            bf[nf][0] = Ws[nb][kk + c0];
            bf[nf][1] = Ws[nb][kk + c0 + 4];
        }
        #pragma unroll
        for (int mf=0; mf<2; mf++)
            #pragma unroll
            for (int nf=0; nf<4; nf++)
                mma_tf32(acc[mf][nf], af[mf], bf[nf][0], bf[nf][1]);
    }
    #pragma unroll
    for (int mf=0; mf<2; mf++){
        int row = wm*32 + mf*16 + r0;
        #pragma unroll
        for (int nf=0; nf<4; nf++){
            int col = n0 + wn*32 + nf*8 + 2*c0;
            *(float2*)&C[(size_t)row*ldc + col] = make_float2(acc[mf][nf][0], acc[mf][nf][1]);
            *(float2*)&C[(size_t)(row+8)*ldc + col] = make_float2(acc[mf][nf][2], acc[mf][nf][3]);
        }
    }
}

// ---------------- setup kernels ----------------
__global__ void zero_init(){
    int i0 = blockIdx.x*blockDim.x + threadIdx.x;
    if (i0 == 0) g_cnt = 0u;
    for (int i=i0;i<BB*EE;i+=gridDim.x*blockDim.x) g_f[i]=0.f;
}

__global__ void cvt_w(const float* __restrict__ outW){
    int stride = gridDim.x*blockDim.x;
    for (int i = blockIdx.x*blockDim.x + threadIdx.x; i < NT*128*512; i += stride){
        int r = i >> 9;
        g_w16[i] = __float2bfloat16(r < VV ? outW[i] : 0.f);
    }
}

__global__ void fold_kernel(const float* __restrict__ wih, const float* __restrict__ combW){
    __shared__ float As[32][132];
    __shared__ float Bs[32][68];
    int m0 = blockIdx.y * 128, n0 = blockIdx.x * 64;
    int tid = threadIdx.x, cx = tid & 15, ry = tid >> 4;
    float acc[8][4];
    for (int i=0;i<8;i++)
        for (int j=0;j<4;j++) acc[i][j]=0.f;
    for (int k0=0;k0<512;k0+=32){
        #pragma unroll
        for (int i=0;i<4;i++){
            int idx = tid + i*256;
            int m = idx >> 3, q = idx & 7;
            float4 v = ld4(&wih[(m0+m)*512 + k0 + 4*q]);
            As[4*q+0][m]=v.x; As[4*q+1][m]=v.y; As[4*q+2][m]=v.z; As[4*q+3][m]=v.w;
        }
        #pragma unroll
        for (int i=0;i<2;i++){
            int f4 = tid + i*256;
            int k = f4 >> 4, n4 = f4 & 15;
            *(float4*)&Bs[k][n4*4] = ld4(&combW[(k0+k)*1024 + n0 + n4*4]);
        }
        __syncthreads();
        #pragma unroll
        for (int k=0;k<32;k++){
            float4 a0=ld4(&As[k][8*ry]), a1=ld4(&As[k][8*ry+4]);
            float4 w=ld4(&Bs[k][4*cx]);
            float av[8]={a0.x,a0.y,a0.z,a0.w,a1.x,a1.y,a1.z,a1.w};
            float wv[4]={w.x,w.y,w.z,w.w};
            #pragma unroll
            for(int i=0;i<8;i++)
              #pragma unroll
              for(int j=0;j<4;j++)
                acc[i][j] = fmaf(av[i], wv[j], acc[i][j]);
        }
        __syncthreads();
    }
    #pragma unroll
    for(int i=0;i<8;i++)
        #pragma unroll
        for(int j=0;j<4;j++)
            g_Wf[(size_t)(m0+8*ry+i)*1024 + n0+4*cx+j] = acc[i][j];
}

__global__ void gb_kernel(const float* __restrict__ wih, const float* __restrict__ bih,
                          const float* __restrict__ comb_b){
    int a = blockIdx.x*8 + (threadIdx.x >> 5);
    int lane = threadIdx.x & 31;
    float s = 0.f;
    for (int c = lane; c < 512; c += 32) s += comb_b[c]*wih[(size_t)a*512 + c];
    #pragma unroll
    for (int o=16;o;o>>=1) s += __shfl_xor_sync(0xFFFFFFFFu, s, o);
    if (lane == 0) g_gb[a] = s + bih[a];
}

__global__ void fc_kernel(const float* __restrict__ features,
                          const float* __restrict__ fcW, const float* __restrict__ fcb){
    __shared__ float As[32][132]; __shared__ float Ws[32][68];
    int tile = blockIdx.x & 7, split = blockIdx.x >> 3;
    int tid = threadIdx.x, cx = tid & 15, ry = tid >> 4;
    int n0 = tile*64, kBeg = split*128;
    float acc[8][4];
    for (int i=0;i<8;i++)
        for (int j=0;j<4;j++) acc[i][j]=0.f;
    for (int k0 = kBeg; k0 < kBeg+128; k0 += 32) {
        #pragma unroll
        for (int i=0;i<4;i++){
            int idx = tid + i*256;
            int m = idx >> 3, q = idx & 7;
            float4 v = ld4(&features[m*FIN + k0 + 4*q]);
            As[4*q+0][m]=v.x; As[4*q+1][m]=v.y; As[4*q+2][m]=v.z; As[4*q+3][m]=v.w;
        }
        #pragma unroll
        for (int i=0;i<2;i++){
            int idx = tid + i*256;
            int n = idx >> 3, q = idx & 7;
            float4 v = ld4(&fcW[(n0+n)*FIN + k0 + 4*q]);
            Ws[4*q+0][n]=v.x; Ws[4*q+1][n]=v.y; Ws[4*q+2][n]=v.z; Ws[4*q+3][n]=v.w;
        }
        __syncthreads();
        #pragma unroll
        for (int k=0;k<32;k++){
            float4 a0 = ld4(&As[k][8*ry]);
            float4 a1 = ld4(&As[k][8*ry+4]);
            float4 w  = ld4(&Ws[k][4*cx]);
            float av[8] = {a0.x,a0.y,a0.z,a0.w,a1.x,a1.y,a1.z,a1.w};
            float wv[4] = {w.x,w.y,w.z,w.w};
            #pragma unroll
            for(int i=0;i<8;i++)
              #pragma unroll
              for(int j=0;j<4;j++)
                acc[i][j] = fmaf(av[i], wv[j], acc[i][j]);
        }
        __syncthreads();
    }
    #pragma unroll
    for(int i=0;i<8;i++){
        int m = 8*ry + i;
        #pragma unroll
        for(int j=0;j<4;j++){
            int n = n0 + 4*cx + j;
            float v = acc[i][j];
            if (split == 0) v += fcb[n];
            atomicAdd(&g_f[m*EE + n], v);
        }
    }
}

__global__ void bn_kernel(const float* __restrict__ gamma, const float* __restrict__ beta){
    __shared__ float s1[16][17], s2[16][17];
    int jc = threadIdx.x & 15, rg = threadIdx.x >> 4;
    int j = blockIdx.x*16 + jc;
    float sum=0.f, sq=0.f;
    for (int i=0;i<8;i++){
        float v = g_f[(rg*8+i)*512 + j];
        sum += v; sq += v*v;
    }
    s1[jc][rg]=sum; s2[jc][rg]=sq;
    __syncthreads();
    if (rg == 0){
        float a=0.f,bq=0.f;
        for (int i=0;i<16;i++){ a+=s1[jc][i]; bq+=s2[jc][i]; }
        float mu = a*(1.f/128.f);
        s1[jc][16]=mu; s2[jc][16]=rsqrtf(bq*(1.f/128.f)-mu*mu+1e-5f);
    }
    __syncthreads();
    float mu=s1[jc][16], rstd=s2[jc][16];
    float ga=gamma[j], be=beta[j];
    for (int i=0;i<8;i++){
        int idx=(rg*8+i)*512 + j;
        g_feats[idx] = ga*(g_f[idx]-mu)*rstd + be;
    }
}

__global__ void prep_kernel(const int* __restrict__ captions,
                            const float* __restrict__ embed_W,
                            const float* __restrict__ h0){
    int stride = gridDim.x*blockDim.x;
    for (int gi = blockIdx.x*blockDim.x + threadIdx.x; gi < TT*BB*EE; gi += stride){
        int t = gi >> 16, idx = gi & 65535;
        int b = idx >> 9, e = idx & 511;
        float v;
        if (t == 0) v = g_feats[idx];
        else { int cap = captions[b*TT + (t-1)]; v = embed_W[cap*EE + e]; }
        g_x[gi] = v;
    }
    for (int i = blockIdx.x*blockDim.x + threadIdx.x; i < BB*HH; i += stride)
        g_h[i] = h0[i];
}

// ---------------- bulk tf32 precompute ----------------
__global__ void bulk_ax(const float* __restrict__ attn_W, const float* __restrict__ attn_b){
    extern __shared__ float sm[];
    tf32_tile<false>(g_x + (size_t)blockIdx.y*128*512, 512, attn_W, 1024,
                     g_Ax + (size_t)blockIdx.y*128*512, 512, blockIdx.x*64, 0, 4, attn_b, sm);
}
__global__ void bulk_gx(){
    extern __shared__ float sm[];
    tf32_tile<false>(g_x + (size_t)blockIdx.y*128*512, 512, g_Wf, 1024,
                     g_Gx + (size_t)blockIdx.y*128*1536, 1536, blockIdx.x*64, 0, 4, g_gb, sm);
}

// ---------------- persistent recurrence (weight-stationary) ----------------
__global__ __launch_bounds__(256,1) void recur_kernel(const float* __restrict__ attn_W,
                                                      const float* __restrict__ whh,
                                                      const float* __restrict__ bhh,
                                                      float* __restrict__ out_hidden){
    extern __shared__ float sm[];
    __shared__ float red[256];
    const int bid = blockIdx.x, tid = threadIdx.x;
    uint32_t (*Wc1)[132] = (uint32_t(*)[132])(sm + 128*132);
    uint32_t (*Wc2)[132] = (uint32_t(*)[132])(sm + 192*132);
    unsigned target = 0;

    // ---- one-time W preload (tf32 bits) ----
    int p1_tile = 0, p1_sp = 0;
    if (bid < 32){
        p1_tile = bid >> 2; p1_sp = bid & 3;
        w_preload(attn_W + 512, 1024, p1_tile*64, p1_sp*128, Wc1);
    } else if (bid < 128){
        int q = bid - 32; p1_tile = q >> 2; p1_sp = q & 3;
        w_preload(whh, 512, p1_tile*64, p1_sp*128, Wc1);
    }
    int p3_tile = bid >> 2, p3_sp = bid & 3;
    if (bid < 96)
        w_preload(g_Wf + 512, 1024, p3_tile*64, p3_sp*128, Wc2);
    __syncthreads();

    for (int t = 0; t < TT; t++){
        // P1: al partials / gh partials (weight-stationary)
        if (bid < 32){
            tf32_tile_c(g_h, 512, g_sp_al + p1_sp*BB*512, 512,
                        p1_tile*64, p1_sp*128, sm, Wc1);
        } else if (bid < 128){
            tf32_tile_c(g_h, 512, g_sp_gh + p1_sp*BB*1536, 1536,
                        p1_tile*64, p1_sp*128, sm, Wc1);
        }
        target += GRID_R; gsync(target);

        // P2: softmax + applied
        if (bid < 128){
            int b = bid;
            const float* ax = g_Ax + ((size_t)t*128 + b)*512;
            float v0 = ax[tid], v1 = ax[tid+256];
            #pragma unroll
            for (int s=0;s<4;s++){
                v0 += __ldcg(&g_sp_al[s*BB*512 + b*512 + tid]);
                v1 += __ldcg(&g_sp_al[s*BB*512 + b*512 + 256 + tid]);
            }
            float m = fmaxf(v0,v1);
            red[tid]=m; __syncthreads();
            for (int s=128;s;s>>=1){ if(tid<s) red[tid]=fmaxf(red[tid],red[tid+s]); __syncthreads(); }
            float mx = red[0]; __syncthreads();
            float e0=expf(v0-mx), e1=expf(v1-mx);
            red[tid]=e0+e1; __syncthreads();
            for (int s=128;s;s>>=1){ if(tid<s) red[tid]+=red[tid+s]; __syncthreads(); }
            float inv = 1.f/red[0];
            g_aw[b*512+tid]     = e0*inv*g_feats[b*512+tid];
            g_aw[b*512+256+tid] = e1*inv*g_feats[b*512+256+tid];
        }
        target += GRID_R; gsync(target);

        // P3: gx partials (weight-stationary)
        if (bid < 96){
            tf32_tile_c(g_aw, 512, g_sp_gx + p3_sp*BB*1536, 1536,
                        p3_tile*64, p3_sp*128, sm, Wc2);
        }
        target += GRID_R; gsync(target);

        // P4: GRU combine
        for (int idx = bid*256 + tid; idx < BB*HH; idx += GRID_R*256){
            int b = idx >> 9, j = idx & 511;
            size_t r = (size_t)t*128 + b;
            float xr = g_Gx[r*1536 + j],        hr = bhh[j];
            float xz = g_Gx[r*1536 + j + 512],  hz = bhh[j+512];
            float xn = g_Gx[r*1536 + j + 1024], hn = bhh[j+1024];
            #pragma unroll
            for (int s=0;s<4;s++){
                const float* px = g_sp_gx + s*BB*1536 + b*1536;
                const float* ph = g_sp_gh + s*BB*1536 + b*1536;
                xr += __ldcg(px + j);        hr += __ldcg(ph + j);
                xz += __ldcg(px + j + 512);  hz += __ldcg(ph + j + 512);
                xn += __ldcg(px + j + 1024); hn += __ldcg(ph + j + 1024);
            }
            float hx = g_h[idx];
            float rg = 1.f/(1.f+expf(-(xr+hr)));
            float zg = 1.f/(1.f+expf(-(xz+hz)));
            float nt = tanhf(xn + rg*hn);
            float h = (1.f-zg)*nt + zg*hx;
            g_h[idx] = h;
            out_hidden[(size_t)b*(TT*HH) + t*HH + j] = h;
            g_pk16[r*512 + j] = __float2bfloat16(h);
        }
        target += GRID_R; gsync(target);
    }
}

// ---------------- HMMA bf16 logits GEMM (double-buffered cp.async) ----------------
__global__ __launch_bounds__(256) void out_gemm_mma(const float* __restrict__ outb,
                                                    float* __restrict__ logits){
    extern __shared__ __nv_bfloat16 sm16[];
    __shared__ float s_bias[128];
    const int tid = threadIdx.x, lane = tid & 31, wid = tid >> 5;
    const int wm = wid & 3, wn = wid >> 2;
    const int m0 = blockIdx.y * 128, n0 = blockIdx.x * 128;
    if (tid < 128){ int n = n0 + tid; s_bias[tid] = (n < VV) ? outb[n] : 0.f; }

    __nv_bfloat16* Abase = sm16;
    __nv_bfloat16* Bbase = sm16 + 2*128*APAD;

    float acc[2][8][4];
    #pragma unroll
    for (int i=0;i<2;i++)
        #pragma unroll
        for (int j=0;j<8;j++)
            #pragma unroll
            for (int q=0;q<4;q++) acc[i][j][q]=0.f;

    const __nv_bfloat16* Ag = g_pk16 + (size_t)m0 * 512;
    const __nv_bfloat16* Bg = g_w16  + (size_t)n0 * 512;
    const int lrow = lane & 15, lkh = (lane >> 4) * 8;

    #pragma unroll
    for (int j = 0; j < 4; j++){
        int idx = tid + j*256;
        int r = idx >> 3, cv = idx & 7;
        cpasync16(smem_u32(Abase + r*APAD + cv*8), Ag + (size_t)r*512 + cv*8);
        cpasync16(smem_u32(Bbase + r*APAD + cv*8), Bg + (size_t)r*512 + cv*8);
    }
    asm volatile("cp.async.commit_group;" ::: "memory");

    for (int c = 0; c < 8; c++){
        int cur = c & 1, nxt = cur ^ 1;
        if (c + 1 < 8){
            const __nv_bfloat16* An = Ag + (c+1)*64;
            const __nv_bfloat16* Bn = Bg + (c+1)*64;
            __nv_bfloat16* Ad = Abase + nxt*128*APAD;
            __nv_bfloat16* Bd = Bbase + nxt*128*APAD;
            #pragma unroll
            for (int j = 0; j < 4; j++){
                int idx = tid + j*256;
                int r = idx >> 3, cv = idx & 7;
                cpasync16(smem_u32(Ad + r*APAD + cv*8), An + (size_t)r*512 + cv*8);
                cpasync16(smem_u32(Bd + r*APAD + cv*8), Bn + (size_t)r*512 + cv*8);
            }
            asm volatile("cp.async.commit_group;" ::: "memory");
            asm volatile("cp.async.wait_group 1;" ::: "memory");
        } else {
            asm volatile("cp.async.wait_group 0;" ::: "memory");
        }
        __syncthreads();
        const __nv_bfloat16* Ac = Abase + cur*128*APAD;
        const __nv_bfloat16* Bc = Bbase + cur*128*APAD;
        #pragma unroll
        for (int ks = 0; ks < 4; ks++){
            int kk = ks*16;
            uint32_t a[2][4];
            #pragma unroll
            for (int mt=0; mt<2; mt++){
                uint32_t ad = smem_u32(Ac + (wm*32 + mt*16 + lrow)*APAD + kk + lkh);
                ldm4(a[mt], ad);
            }
            uint32_t b[4][4];
            #pragma unroll
            for (int nt=0; nt<4; nt++){
                uint32_t bd = smem_u32(Bc + (wn*64 + nt*16 + lrow)*APAD + kk + lkh);
                ldm4(b[nt], bd);
            }
            #pragma unroll
            for (int mt=0; mt<2; mt++)
                #pragma unroll
                for (int nt=0; nt<4; nt++){
                    mma16816(acc[mt][nt*2+0], a[mt], b[nt][0], b[nt][2]);
                    mma16816(acc[mt][nt*2+1], a[mt], b[nt][1], b[nt][3]);
                }
        }
        __syncthreads();
    }
    const int r0 = lane >> 2, c2 = (lane & 3) * 2;
    #pragma unroll
    for (int mt=0; mt<2; mt++){
        int row = m0 + wm*32 + mt*16 + r0;
        #pragma unroll
        for (int nt=0; nt<8; nt++){
            int lcol = wn*64 + nt*8 + c2;
            int col  = n0 + lcol;
            if (col < VV){
                float2 v0, v1;
                v0.x = acc[mt][nt][0] + s_bias[lcol];
                v0.y = acc[mt][nt][1] + s_bias[lcol+1];
                v1.x = acc[mt][nt][2] + s_bias[lcol];
                v1.y = acc[mt][nt][3] + s_bias[lcol+1];
                *(float2*)&logits[(size_t)row * VV + col] = v0;
                *(float2*)&logits[(size_t)(row+8) * VV + col] = v1;
            }
        }
    }
}

__global__ __launch_bounds__(512) void lsm_kernel(float* __restrict__ logits){
    __shared__ float red[512];
    int row = blockIdx.x, tid = threadIdx.x;
    float* p = logits + (size_t)row*VV;
    float4 v[5];
    int n = 0;
    float m = -1e30f;
    for (int i = tid; i < 2500; i += 512){
        float4 x = ld4(p + i*4);
        v[n++] = x;
        m = fmaxf(m, fmaxf(fmaxf(x.x,x.y), fmaxf(x.z,x.w)));
    }
    red[tid]=m; __syncthreads();
    for (int s=256;s;s>>=1){ if(tid<s) red[tid]=fmaxf(red[tid],red[tid+s]); __syncthreads(); }
    float mx = red[0]; __syncthreads();
    float sum = 0.f;
    for (int i=0;i<n;i++)
        sum += expf(v[i].x-mx)+expf(v[i].y-mx)+expf(v[i].z-mx)+expf(v[i].w-mx);
    red[tid]=sum; __syncthreads();
    for (int s=256;s;s>>=1){ if(tid<s) red[tid]+=red[tid+s]; __syncthreads(); }
    float lse = mx + logf(red[0]);
    n = 0;
    for (int i = tid; i < 2500; i += 512){
        float4 x = v[n++];
        x.x -= lse; x.y -= lse; x.z -= lse; x.w -= lse;
        *(float4*)(p + i*4) = x;
    }
}

// ---------------- launch ----------------
extern "C" void kernel_launch(void* const* d_in, const int* in_sizes, int n_in,
                              void* d_out, int out_size){
    const float* features = (const float*)d_in[0];
    const int*   captions = (const int*)  d_in[1];
    const float* h0       = (const float*)d_in[2];
    const float* embed_W  = (const float*)d_in[4];
    const float* fc_W     = (const float*)d_in[5];
    const float* fc_b     = (const float*)d_in[6];
    const float* bn_gamma = (const float*)d_in[7];
    const float* bn_beta  = (const float*)d_in[8];
    const float* attn_W   = (const float*)d_in[9];
    const float* attn_b   = (const float*)d_in[10];
    const float* comb_W   = (const float*)d_in[11];
    const float* comb_b   = (const float*)d_in[12];
    const float* gru_Wih  = (const float*)d_in[13];
    const float* gru_Whh  = (const float*)d_in[14];
    const float* gru_bih  = (const float*)d_in[15];
    const float* gru_bhh  = (const float*)d_in[16];
    const float* out_W    = (const float*)d_in[17];
    const float* out_b    = (const float*)d_in[18];

    float* out     = (float*)d_out;
    float* logits  = out;
    float* hiddens = out + (size_t)TB*VV;

    static bool attr_set = false;
    if (!attr_set){
        cudaFuncSetAttribute(bulk_ax, cudaFuncAttributeMaxDynamicSharedMemorySize, SMEM_TILE);
        cudaFuncSetAttribute(bulk_gx, cudaFuncAttributeMaxDynamicSharedMemorySize, SMEM_TILE);
        cudaFuncSetAttribute(recur_kernel, cudaFuncAttributeMaxDynamicSharedMemorySize, SMEM_TILE);
        cudaFuncSetAttribute(out_gemm_mma, cudaFuncAttributeMaxDynamicSharedMemorySize, OG_SMEM);
        attr_set = true;
    }

    zero_init<<<128,256>>>();
    cvt_w<<<2048,256>>>(out_W);
    fold_kernel<<<dim3(16,12),256>>>(gru_Wih, comb_W);
    gb_kernel<<<192,256>>>(gru_Wih, gru_bih, comb_b);
    fc_kernel<<<128,256>>>(features, fc_W, fc_b);
    bn_kernel<<<32,256>>>(bn_gamma, bn_beta);
    prep_kernel<<<1024,256>>>(captions, embed_W, h0);
    bulk_ax<<<dim3(8,64),256,SMEM_TILE>>>(attn_W, attn_b);
    bulk_gx<<<dim3(24,64),256,SMEM_TILE>>>();
    recur_kernel<<<GRID_R,256,SMEM_TILE>>>(attn_W, gru_Whh, gru_bhh, hiddens);
    out_gemm_mma<<<dim3(NT,64),256,OG_SMEM>>>(out_b, logits);
    lsm_kernel<<<TB,512>>>(logits);
}